// round 7
// baseline (speedup 1.0000x reference)
#include <cuda_runtime.h>
#include <cstdint>

#define NBLKu 128u

// ---------------- device scratch ----------------
__device__ float g_xbuf0[16*128*1024];
__device__ float g_xbuf1[16*128*1024];
__device__ float g_gatesin[2*2048*2048];
__device__ float g_WhhEncT[4*512*2048];
__device__ float g_henc[2*16*512];
__device__ float g_cenc[2*16*512];
__device__ float g_epart[16*16*2048];
__device__ float g_hdec[2*16*1024];
__device__ float g_cdec[2*16*1024];
__device__ float g_demb[16*128*1024];
__device__ float g_preL0[2048*4096];
__device__ float g_WdecT0[2048*4096];
__device__ float g_WdecT1[2048*4096];
__device__ float g_lininT[1024*1024];
__device__ float g_linoutT[2048*1024];
__device__ float g_op[16*1024];
__device__ float g_cc[16*1024];
__device__ float g_part0[8*16*4096];
__device__ float g_part1[8*16*4096];
__device__ float g_q[16*1024];
__device__ float g_lopart[32*16*1024];
__device__ float g_opn[2048*1024];
__device__ unsigned g_barA, g_barG;

// ---------------- helpers ----------------
__device__ __forceinline__ float2 ffma2(float2 a, float2 b, float2 c) {
    unsigned long long ra = *reinterpret_cast<unsigned long long*>(&a);
    unsigned long long rb = *reinterpret_cast<unsigned long long*>(&b);
    unsigned long long rc = *reinterpret_cast<unsigned long long*>(&c);
    unsigned long long rd;
    asm("fma.rn.f32x2 %0, %1, %2, %3;" : "=l"(rd) : "l"(ra), "l"(rb), "l"(rc));
    return *reinterpret_cast<float2*>(&rd);
}
__device__ __forceinline__ float sigf(float x) { return 1.0f / (1.0f + expf(-x)); }

// cooperative-groups-style grid barrier: no per-thread fences.
__device__ __forceinline__ void gridbar() {
    __syncthreads();
    if (threadIdx.x == 0) {
        unsigned gen;
        asm volatile("ld.volatile.global.u32 %0, [%1];" : "=r"(gen) : "l"(&g_barG));
        unsigned prev;
        asm volatile("atom.release.gpu.global.add.u32 %0, [%1], 1;"
                     : "=r"(prev) : "l"(&g_barA) : "memory");
        if (prev == NBLKu - 1u) {
            asm volatile("st.global.u32 [%0], 0;" :: "l"(&g_barA) : "memory");
            asm volatile("st.release.gpu.global.u32 [%0], %1;"
                         :: "l"(&g_barG), "r"(gen + 1u) : "memory");
        } else {
            unsigned cur;
            do {
                asm volatile("ld.acquire.gpu.global.u32 %0, [%1];"
                             : "=r"(cur) : "l"(&g_barG) : "memory");
            } while (cur == gen);
        }
    }
    __syncthreads();
}

// ---------------- prep: all transposes + embeddings ----------------
__global__ void __launch_bounds__(256) k_prep(
    const float* __restrict__ enc_emb, const float* __restrict__ dec_emb,
    const float* __restrict__ enc_Whh, const float* __restrict__ dec_Wih0,
    const float* __restrict__ dec_Wih_rest, const float* __restrict__ dec_Whh,
    const float* __restrict__ linin_W, const float* __restrict__ linout_W,
    const int* __restrict__ inp, const int* __restrict__ outtok) {
    unsigned id = blockIdx.x;
    int tid = threadIdx.x;
    if (id >= 23552u) {
        if (id < 31744u) {
            int i = (int)(id - 23552u) * 256 + tid;
            int h = i & 1023, tok = i >> 10;
            g_xbuf0[i] = enc_emb[(size_t)inp[tok] * 1024 + h];
        } else {
            int i = (int)(id - 31744u) * 256 + tid;
            int h = i & 1023, bt = i >> 10;
            int b = bt >> 7, t = bt & 127;
            int tk = (t == 0) ? 3 : outtok[b*128 + t - 1];
            g_demb[i] = dec_emb[(size_t)tk * 1024 + h];
        }
        return;
    }
    const float* in; float* out; int R, C, ld, col0; unsigned tile;
    if (id < 4096u)       { unsigned l4 = id >> 10; tile = id & 1023u;
                            in = enc_Whh + (size_t)l4*2048*512; out = g_WhhEncT + (size_t)l4*512*2048;
                            R = 2048; C = 512; ld = 512; col0 = 0; }
    else if (id < 8192u)  { tile = id - 4096u;  in = dec_Wih0;     out = g_WdecT0;
                            R = 4096; C = 1024; ld = 2048; col0 = 1024; }
    else if (id < 12288u) { tile = id - 8192u;  in = dec_Whh;      out = g_WdecT0 + (size_t)1024*4096;
                            R = 4096; C = 1024; ld = 1024; col0 = 0; }
    else if (id < 16384u) { tile = id - 12288u; in = dec_Wih_rest; out = g_WdecT1;
                            R = 4096; C = 1024; ld = 1024; col0 = 0; }
    else if (id < 20480u) { tile = id - 16384u; in = dec_Whh + (size_t)4096*1024; out = g_WdecT1 + (size_t)1024*4096;
                            R = 4096; C = 1024; ld = 1024; col0 = 0; }
    else if (id < 21504u) { tile = id - 20480u; in = linin_W;      out = g_lininT;
                            R = 1024; C = 1024; ld = 1024; col0 = 0; }
    else                  { tile = id - 21504u; in = linout_W;     out = g_linoutT;
                            R = 1024; C = 2048; ld = 2048; col0 = 0; }
    __shared__ float ts[32][33];
    int cbn = C >> 5;
    int cb = ((int)tile % cbn) << 5, rb = ((int)tile / cbn) << 5;
    int tx = tid & 31, ty = tid >> 5;
    #pragma unroll
    for (int i = 0; i < 32; i += 8)
        ts[ty + i][tx] = in[(size_t)(rb + ty + i) * ld + col0 + cb + tx];
    __syncthreads();
    #pragma unroll
    for (int i = 0; i < 32; i += 8)
        out[(size_t)(cb + ty + i) * R + rb + tx] = ts[tx][ty + i];
}

// ---------------- tiled GEMM tile (device fn) ----------------
__device__ __forceinline__ void gemm128(
    const float* __restrict__ A, int lda,
    const float* __restrict__ W, int ldw,
    const float* __restrict__ bias,
    float* __restrict__ C, int ldc, int K, int mt, int nt) {
    __shared__ float As[16][132];
    __shared__ float Bs[16][132];
    int tid = threadIdx.x;
    int tx = tid & 15, ty = tid >> 4;
    size_t mb = (size_t)mt * 128, nb = (size_t)nt * 128;
    float2 acc[8][4];
    #pragma unroll
    for (int i = 0; i < 8; i++)
        #pragma unroll
        for (int j = 0; j < 4; j++) acc[i][j] = make_float2(0.f, 0.f);
    int lr = tid >> 2, lc4 = (tid & 3) * 4;
    const float* Ap  = A + (mb + lr) * (size_t)lda + lc4;
    const float* Ap2 = Ap + (size_t)64 * lda;
    const float* Wp  = W + (nb + lr) * (size_t)ldw + lc4;
    const float* Wp2 = Wp + (size_t)64 * ldw;
    for (int k0 = 0; k0 < K; k0 += 16) {
        float4 a0 = *(const float4*)(Ap  + k0);
        float4 a1 = *(const float4*)(Ap2 + k0);
        float4 b0 = *(const float4*)(Wp  + k0);
        float4 b1 = *(const float4*)(Wp2 + k0);
        As[lc4+0][lr] = a0.x; As[lc4+1][lr] = a0.y; As[lc4+2][lr] = a0.z; As[lc4+3][lr] = a0.w;
        As[lc4+0][lr+64] = a1.x; As[lc4+1][lr+64] = a1.y; As[lc4+2][lr+64] = a1.z; As[lc4+3][lr+64] = a1.w;
        Bs[lc4+0][lr] = b0.x; Bs[lc4+1][lr] = b0.y; Bs[lc4+2][lr] = b0.z; Bs[lc4+3][lr] = b0.w;
        Bs[lc4+0][lr+64] = b1.x; Bs[lc4+1][lr+64] = b1.y; Bs[lc4+2][lr+64] = b1.z; Bs[lc4+3][lr+64] = b1.w;
        __syncthreads();
        #pragma unroll
        for (int kk = 0; kk < 16; kk++) {
            float4 av0 = *(const float4*)&As[kk][ty*8];
            float4 av1 = *(const float4*)&As[kk][ty*8+4];
            float4 bv0 = *(const float4*)&Bs[kk][tx*8];
            float4 bv1 = *(const float4*)&Bs[kk][tx*8+4];
            float a8[8] = {av0.x,av0.y,av0.z,av0.w,av1.x,av1.y,av1.z,av1.w};
            float2 bp[4];
            bp[0] = make_float2(bv0.x, bv0.y); bp[1] = make_float2(bv0.z, bv0.w);
            bp[2] = make_float2(bv1.x, bv1.y); bp[3] = make_float2(bv1.z, bv1.w);
            #pragma unroll
            for (int i = 0; i < 8; i++) {
                float2 ai = make_float2(a8[i], a8[i]);
                #pragma unroll
                for (int j = 0; j < 4; j++) acc[i][j] = ffma2(ai, bp[j], acc[i][j]);
            }
        }
        __syncthreads();
    }
    float bsv[8];
    #pragma unroll
    for (int j = 0; j < 8; j++) bsv[j] = bias[nb + tx*8 + j];
    #pragma unroll
    for (int i = 0; i < 8; i++) {
        float* Cp = C + (mb + ty*8 + i) * (size_t)ldc + nb + tx*8;
        float4 o0, o1;
        o0.x = acc[i][0].x + bsv[0]; o0.y = acc[i][0].y + bsv[1];
        o0.z = acc[i][1].x + bsv[2]; o0.w = acc[i][1].y + bsv[3];
        o1.x = acc[i][2].x + bsv[4]; o1.y = acc[i][2].y + bsv[5];
        o1.z = acc[i][3].x + bsv[6]; o1.w = acc[i][3].y + bsv[7];
        *(float4*)Cp = o0;
        *(float4*)(Cp + 4) = o1;
    }
}

// launch 1: enc layer-0 gates (both dirs) + decoder preL0 — all depend only on prep
__global__ void __launch_bounds__(256) k_gemmA(
    const float* __restrict__ enc_Wih, const float* __restrict__ enc_b,
    const float* __restrict__ dec_Wih0, const float* __restrict__ dec_b) {
    int id = blockIdx.x;
    if (id < 256)
        gemm128(g_xbuf0, 1024, enc_Wih, 1024, enc_b, g_gatesin, 2048, 1024, id >> 4, id & 15);
    else if (id < 512) {
        int j = id - 256;
        gemm128(g_xbuf0, 1024, enc_Wih + (size_t)2048*1024, 1024, enc_b + 2048,
                g_gatesin + (size_t)2048*2048, 2048, 1024, j >> 4, j & 15);
    } else {
        int j = id - 512;
        gemm128(g_demb, 1024, dec_Wih0, 2048, dec_b, g_preL0, 4096, 1024, j >> 5, j & 31);
    }
}

// launch 3: enc layer-1 gates (both dirs) from xbuf1
__global__ void __launch_bounds__(256) k_gemmL1(
    const float* __restrict__ enc_Wih, const float* __restrict__ enc_b) {
    int id = blockIdx.x;
    int d = id >> 8, j = id & 255;
    gemm128(g_xbuf1, 1024, enc_Wih + (size_t)(2 + d)*2048*1024, 1024, enc_b + (2 + d)*2048,
            g_gatesin + (size_t)d*2048*2048, 2048, 1024, j >> 4, j & 15);
}

__global__ void __launch_bounds__(256) k_gemmGen(
    const float* __restrict__ gen_W, const float* __restrict__ gen_b,
    float* __restrict__ logits) {
    gemm128(g_opn, 1024, gen_W, 1024, gen_b, logits, 32000, 1024, blockIdx.y, blockIdx.x);
}

// ---------------- persistent encoder layer: 128 x 256 ----------------
__global__ void __launch_bounds__(256) k_enc_persist(
    const float* __restrict__ WhhT, float* __restrict__ xout,
    float* __restrict__ hd_slot, float* __restrict__ cd_slot) {
    __shared__ float sbuf[1024];
    int tid = threadIdx.x, bid = blockIdx.x;
    int gi = bid * 256 + tid;
    float* h = g_henc; float* c = g_cenc;

    if (gi < 2*16*512) { h[gi] = 0.f; c[gi] = 0.f; }
    gridbar();

    int d  = bid >> 6;
    int nc = (bid >> 3) & 7;
    int kc = bid & 7;
    int kbase = kc * 64;
    int n = nc * 256 + tid;
    const float* hv = h + d * 16 * 512;
    const float* wp = WhhT + (size_t)d * 512 * 2048 + (size_t)kbase * 2048 + n;
    float* pp = g_epart + (size_t)((d*8 + kc) * 16) * 2048 + n;

    for (int s = 0; s < 128; s++) {
        for (int i = tid; i < 64*16; i += 256) {
            int k = i >> 4, b = i & 15;
            sbuf[i] = hv[b*512 + kbase + k];
        }
        __syncthreads();
        {
            const float2* vs2 = (const float2*)sbuf;
            float2 acc[8];
            #pragma unroll
            for (int bp = 0; bp < 8; bp++) acc[bp] = make_float2(0.f, 0.f);
            #pragma unroll 8
            for (int k = 0; k < 64; k++) {
                float w = wp[(size_t)k * 2048];
                float2 w2 = make_float2(w, w);
                #pragma unroll
                for (int bp = 0; bp < 8; bp++) acc[bp] = ffma2(w2, vs2[k*8+bp], acc[bp]);
            }
            #pragma unroll
            for (int bp = 0; bp < 8; bp++) {
                pp[(size_t)(2*bp)   * 2048] = acc[bp].x;
                pp[(size_t)(2*bp+1) * 2048] = acc[bp].y;
            }
        }
        gridbar();
        if (gi < 16384) {
            int dd = gi >> 13, j = gi & 8191;
            int b = j >> 9, hh = j & 511;
            int sdir = dd ? (127 - s) : s;
            const float* gin = g_gatesin + ((size_t)dd*2048 + b*128 + sdir) * 2048;
            float g4[4];
            #pragma unroll
            for (int q4 = 0; q4 < 4; q4++) {
                int nn = q4*512 + hh;
                float v = gin[nn];
                #pragma unroll
                for (int k2 = 0; k2 < 8; k2++)
                    v += g_epart[(size_t)((dd*8 + k2)*16 + b)*2048 + nn];
                g4[q4] = v;
            }
            int idx = (dd*16 + b)*512 + hh;
            float cn = sigf(g4[1]) * c[idx] + sigf(g4[0]) * tanhf(g4[2]);
            float hn = sigf(g4[3]) * tanhf(cn);
            c[idx] = cn; h[idx] = hn;
            xout[((size_t)b*128 + sdir)*1024 + dd*512 + hh] = hn;
        }
        gridbar();
    }
    if (gi < 16384) {
        int b = gi >> 10, hh = gi & 1023;
        float hv2, cv2;
        if (hh < 512) { hv2 = h[b*512 + hh];            cv2 = c[b*512 + hh]; }
        else          { hv2 = h[(16+b)*512 + hh - 512]; cv2 = c[(16+b)*512 + hh - 512]; }
        hd_slot[b*1024 + hh] = hv2;
        cd_slot[b*1024 + hh] = cv2;
    }
}

// ---------------- persistent decoder: 128 x 256 ----------------
__global__ void __launch_bounds__(256) k_dec_persist(
    const float* __restrict__ bias1, const float* __restrict__ enc) {
    __shared__ float sbuf[4096];
    int tid = threadIdx.x, bid = blockIdx.x;
    int gi = bid * 256 + tid;
    float* op = g_op;
    float* hd0 = g_hdec;            float* cd0 = g_cdec;
    float* hd1 = g_hdec + 16*1024;  float* cd1 = g_cdec + 16*1024;

    if (gi < 16*1024) op[gi] = 0.f;
    gridbar();

    int ncA = bid >> 3, kcA = bid & 7;
    int kbaseA = kcA * 256;
    int nA = ncA * 256 + tid;
    int ncG = bid >> 5, kcG = bid & 31;
    int kbaseG = kcG * 64;
    int nG = ncG * 256 + tid;

    for (int t = 0; t < 128; t++) {
        // Phase A
        for (int i = tid; i < 256*16; i += 256) {
            int k = i >> 4, b = i & 15, kg = kbaseA + k;
            sbuf[i] = (kg < 1024) ? op[b*1024 + kg] : hd0[b*1024 + kg - 1024];
        }
        __syncthreads();
        {
            const float2* vs2 = (const float2*)sbuf;
            float2 acc[8];
            #pragma unroll
            for (int bp = 0; bp < 8; bp++) acc[bp] = make_float2(0.f, 0.f);
            const float* wp = g_WdecT0 + (size_t)kbaseA * 4096 + nA;
            #pragma unroll 8
            for (int k = 0; k < 256; k++) {
                float w = wp[(size_t)k * 4096];
                float2 w2 = make_float2(w, w);
                #pragma unroll
                for (int bp = 0; bp < 8; bp++) acc[bp] = ffma2(w2, vs2[k*8+bp], acc[bp]);
            }
            float* pp = g_part0 + (size_t)(kcA*16) * 4096 + nA;
            #pragma unroll
            for (int bp = 0; bp < 8; bp++) {
                pp[(size_t)(2*bp)   * 4096] = acc[bp].x;
                pp[(size_t)(2*bp+1) * 4096] = acc[bp].y;
            }
        }
        gridbar();
        // Phase B: cell0
        if (gi < 16384) {
            int b = gi >> 10, hh = gi & 1023;
            const float* pl = g_preL0 + ((size_t)b*128 + t) * 4096;
            float g4[4];
            #pragma unroll
            for (int q4 = 0; q4 < 4; q4++) {
                int n = q4*1024 + hh;
                float v = pl[n];
                #pragma unroll
                for (int k2 = 0; k2 < 8; k2++) v += g_part0[(size_t)(k2*16 + b)*4096 + n];
                g4[q4] = v;
            }
            int idx = b*1024 + hh;
            float cn = sigf(g4[1]) * cd0[idx] + sigf(g4[0]) * tanhf(g4[2]);
            float hn = sigf(g4[3]) * tanhf(cn);
            cd0[idx] = cn; hd0[idx] = hn;
        }
        gridbar();
        // Phase C
        for (int i = tid; i < 256*16; i += 256) {
            int k = i >> 4, b = i & 15, kg = kbaseA + k;
            sbuf[i] = (kg < 1024) ? hd0[b*1024 + kg] : hd1[b*1024 + kg - 1024];
        }
        __syncthreads();
        {
            const float2* vs2 = (const float2*)sbuf;
            float2 acc[8];
            #pragma unroll
            for (int bp = 0; bp < 8; bp++) acc[bp] = make_float2(0.f, 0.f);
            const float* wp = g_WdecT1 + (size_t)kbaseA * 4096 + nA;
            #pragma unroll 8
            for (int k = 0; k < 256; k++) {
                float w = wp[(size_t)k * 4096];
                float2 w2 = make_float2(w, w);
                #pragma unroll
                for (int bp = 0; bp < 8; bp++) acc[bp] = ffma2(w2, vs2[k*8+bp], acc[bp]);
            }
            float* pp = g_part1 + (size_t)(kcA*16) * 4096 + nA;
            #pragma unroll
            for (int bp = 0; bp < 8; bp++) {
                pp[(size_t)(2*bp)   * 4096] = acc[bp].x;
                pp[(size_t)(2*bp+1) * 4096] = acc[bp].y;
            }
        }
        gridbar();
        // Phase D: cell1
        if (gi < 16384) {
            int b = gi >> 10, hh = gi & 1023;
            float g4[4];
            #pragma unroll
            for (int q4 = 0; q4 < 4; q4++) {
                int n = q4*1024 + hh;
                float v = bias1[n];
                #pragma unroll
                for (int k2 = 0; k2 < 8; k2++) v += g_part1[(size_t)(k2*16 + b)*4096 + n];
                g4[q4] = v;
            }
            int idx = b*1024 + hh;
            float cn = sigf(g4[1]) * cd1[idx] + sigf(g4[0]) * tanhf(g4[2]);
            float hn = sigf(g4[3]) * tanhf(cn);
            cd1[idx] = cn; hd1[idx] = hn;
        }
        gridbar();
        // Phase E: q = hd1 @ lininT  (two accumulators)
        if (gi < 16384) {
            int b = gi >> 10, h = gi & 1023;
            const float* wq = g_lininT + h;
            const float* hv = hd1 + b*1024;
            float a0 = 0.f, a1 = 0.f;
            #pragma unroll 8
            for (int k = 0; k < 1024; k += 2) {
                a0 += wq[(size_t)k * 1024] * hv[k];
                a1 += wq[(size_t)(k+1) * 1024] * hv[k+1];
            }
            g_q[b*1024 + h] = a0 + a1;
        }
        gridbar();
        // Phase F: attention (blocks 0..15)
        if (bid < 16) {
            int b = bid;
            float* qs = sbuf;
            float* scs = sbuf + 1024;
            for (int h = tid; h < 1024; h += 256) qs[h] = g_q[b*1024 + h];
            __syncthreads();
            int wid = tid >> 5, lane = tid & 31;
            for (int s = wid; s < 128; s += 8) {
                const float* e = enc + ((size_t)b*128 + s) * 1024;
                float a = 0.f;
                for (int k = lane; k < 1024; k += 32) a += e[k] * qs[k];
                #pragma unroll
                for (int o = 16; o; o >>= 1) a += __shfl_xor_sync(0xffffffffu, a, o);
                if (!lane) scs[s] = a;
            }
            __syncthreads();
            if (tid < 32) {
                float m = -1e30f;
                for (int s = tid; s < 128; s += 32) m = fmaxf(m, scs[s]);
                #pragma unroll
                for (int o = 16; o; o >>= 1) m = fmaxf(m, __shfl_xor_sync(0xffffffffu, m, o));
                float sum = 0.f;
                for (int s = tid; s < 128; s += 32) { float e2 = expf(scs[s]-m); scs[s] = e2; sum += e2; }
                #pragma unroll
                for (int o = 16; o; o >>= 1) sum += __shfl_xor_sync(0xffffffffu, sum, o);
                float inv = 1.f / sum;
                for (int s = tid; s < 128; s += 32) scs[s] *= inv;
            }
            __syncthreads();
            for (int h = tid; h < 1024; h += 256) {
                float a = 0.f;
                const float* e = enc + (size_t)b*131072 + h;
                #pragma unroll 8
                for (int s = 0; s < 128; s++) a += scs[s] * e[(size_t)s*1024];
                g_cc[b*1024 + h] = a;
            }
        }
        gridbar();
        // Phase G: linout partials from [cc, hd1]
        for (int i = tid; i < 64*16; i += 256) {
            int k = i >> 4, b = i & 15, kg = kbaseG + k;
            sbuf[i] = (kg < 1024) ? g_cc[b*1024 + kg] : hd1[b*1024 + kg - 1024];
        }
        __syncthreads();
        {
            const float2* vs2 = (const float2*)sbuf;
            float2 acc[8];
            #pragma unroll
            for (int bp = 0; bp < 8; bp++) acc[bp] = make_float2(0.f, 0.f);
            const float* wp = g_linoutT + (size_t)kbaseG * 1024 + nG;
            #pragma unroll 8
            for (int k = 0; k < 64; k++) {
                float w = wp[(size_t)k * 1024];
                float2 w2 = make_float2(w, w);
                #pragma unroll
                for (int bp = 0; bp < 8; bp++) acc[bp] = ffma2(w2, vs2[k*8+bp], acc[bp]);
            }
            float* pp = g_lopart + (size_t)(kcG*16) * 1024 + nG;
            #pragma unroll
            for (int bp = 0; bp < 8; bp++) {
                pp[(size_t)(2*bp)   * 1024] = acc[bp].x;
                pp[(size_t)(2*bp+1) * 1024] = acc[bp].y;
            }
        }
        gridbar();
        // Phase H: opn = tanh(sum)
        if (gi < 16384) {
            int b = gi >> 10, hh = gi & 1023;
            float v = 0.f;
            #pragma unroll
            for (int k2 = 0; k2 < 32; k2++) v += g_lopart[(size_t)(k2*16 + b)*1024 + hh];
            float o = tanhf(v);
            op[b*1024 + hh] = o;
            g_opn[((size_t)b*128 + t)*1024 + hh] = o;
        }
        gridbar();
    }
}

// ---------------- host ----------------
#define ADDRF(v) ([]{ void* q_ = nullptr; cudaGetSymbolAddress(&q_, v); return (float*)q_; }())

extern "C" void kernel_launch(void* const* d_in, const int* in_sizes, int n_in,
                              void* d_out, int out_size) {
    const float* enc_emb      = (const float*)d_in[0];
    const float* dec_emb      = (const float*)d_in[1];
    const float* enc_Wih      = (const float*)d_in[2];
    const float* enc_Whh      = (const float*)d_in[3];
    const float* enc_b        = (const float*)d_in[4];
    const float* dec_Wih0     = (const float*)d_in[5];
    const float* dec_Wih_rest = (const float*)d_in[6];
    const float* dec_Whh      = (const float*)d_in[7];
    const float* dec_b        = (const float*)d_in[8];
    const float* linin_W      = (const float*)d_in[9];
    const float* linout_W     = (const float*)d_in[10];
    const float* gen_W        = (const float*)d_in[11];
    const float* gen_b        = (const float*)d_in[12];
    const int*   inp          = (const int*)d_in[13];
    const int*   outtok       = (const int*)d_in[14];
    float* logits = (float*)d_out;

    float* xbuf0   = ADDRF(g_xbuf0);
    float* xbuf1   = ADDRF(g_xbuf1);
    float* WhhEncT = ADDRF(g_WhhEncT);
    float* hdec    = ADDRF(g_hdec);
    float* cdec    = ADDRF(g_cdec);

    // 0: prep (transposes + embeds)
    k_prep<<<39936, 256>>>(enc_emb, dec_emb, enc_Whh, dec_Wih0, dec_Wih_rest,
                           dec_Whh, linin_W, linout_W, inp, outtok);
    // 1: enc layer-0 gates + preL0
    k_gemmA<<<1024, 256>>>(enc_Wih, enc_b, dec_Wih0, dec_b);
    // 2: enc layer 0
    k_enc_persist<<<128, 256>>>(WhhEncT, xbuf1, hdec, cdec);
    // 3: enc layer-1 gates
    k_gemmL1<<<512, 256>>>(enc_Wih, enc_b);
    // 4: enc layer 1
    k_enc_persist<<<128, 256>>>(WhhEncT + (size_t)2*512*2048, xbuf0,
                                hdec + 16*1024, cdec + 16*1024);
    // 5: decoder (profiled by ncu -s 5)
    k_dec_persist<<<128, 256>>>(dec_b + 4096, xbuf0);
    // 6: generator
    k_gemmGen<<<dim3(250, 16), 256>>>(gen_W, gen_b, logits);
}

// round 10
// speedup vs baseline: 1.2761x; 1.2761x over previous
#include <cuda_runtime.h>
#include <cstdint>

#define NBLKu 128u

// ---------------- device scratch ----------------
__device__ float g_xbuf0[16*128*1024];
__device__ float g_xbuf1[16*128*1024];
__device__ float g_gatesin[2*2048*2048];
__device__ float g_WhhEncT[4*512*2048];
__device__ float g_henc[2*16*512];
__device__ float g_cenc[2*16*512];
__device__ float g_epart[16*16*2048];
__device__ float g_hdec[2*16*1024];
__device__ float g_cdec[2*16*1024];
__device__ float g_demb[16*128*1024];
__device__ float g_preL0[2048*4096];
__device__ float g_WdecT0[2048*4096];
__device__ float g_WdecT1[2048*4096];
__device__ float g_lininT[1024*1024];
__device__ float g_linoutT[2048*1024];
__device__ float g_encW[2048*1024];
__device__ float g_scores[16*128];
__device__ float g_zero[1024];
__device__ float g_op[16*1024];
__device__ float g_cc[16*1024];
__device__ float g_part0[8*16*4096];
__device__ float g_part1[8*16*4096];
__device__ float g_lopart[32*16*1024];
__device__ float g_opn[2048*1024];
__device__ unsigned g_barA, g_barG;

// ---------------- helpers ----------------
__device__ __forceinline__ float2 ffma2(float2 a, float2 b, float2 c) {
    unsigned long long ra = *reinterpret_cast<unsigned long long*>(&a);
    unsigned long long rb = *reinterpret_cast<unsigned long long*>(&b);
    unsigned long long rc = *reinterpret_cast<unsigned long long*>(&c);
    unsigned long long rd;
    asm("fma.rn.f32x2 %0, %1, %2, %3;" : "=l"(rd) : "l"(ra), "l"(rb), "l"(rc));
    return *reinterpret_cast<float2*>(&rd);
}
__device__ __forceinline__ float sigf(float x) { return 1.0f / (1.0f + expf(-x)); }

__device__ __forceinline__ void gridbar() {
    __syncthreads();
    if (threadIdx.x == 0) {
        unsigned gen;
        asm volatile("ld.volatile.global.u32 %0, [%1];" : "=r"(gen) : "l"(&g_barG));
        unsigned prev;
        asm volatile("atom.release.gpu.global.add.u32 %0, [%1], 1;"
                     : "=r"(prev) : "l"(&g_barA) : "memory");
        if (prev == NBLKu - 1u) {
            asm volatile("st.global.u32 [%0], 0;" :: "l"(&g_barA) : "memory");
            asm volatile("st.release.gpu.global.u32 [%0], %1;"
                         :: "l"(&g_barG), "r"(gen + 1u) : "memory");
        } else {
            unsigned cur;
            while (true) {
                asm volatile("ld.acquire.gpu.global.u32 %0, [%1];"
                             : "=r"(cur) : "l"(&g_barG) : "memory");
                if (cur != gen) break;
                __nanosleep(64);
            }
        }
    }
    __syncthreads();
}

// ---------------- prep: transposes + embeds ----------------
__global__ void __launch_bounds__(256) k_prep(
    const float* __restrict__ enc_emb, const float* __restrict__ dec_emb,
    const float* __restrict__ enc_Whh, const float* __restrict__ dec_Wih0,
    const float* __restrict__ dec_Wih_rest, const float* __restrict__ dec_Whh,
    const float* __restrict__ linin_W, const float* __restrict__ linout_W,
    const int* __restrict__ inp, const int* __restrict__ outtok) {
    unsigned id = blockIdx.x;
    int tid = threadIdx.x;
    if (id >= 23552u) {
        if (id < 31744u) {
            int i = (int)(id - 23552u) * 256 + tid;
            int h = i & 1023, tok = i >> 10;
            g_xbuf0[i] = enc_emb[(size_t)inp[tok] * 1024 + h];
        } else {
            int i = (int)(id - 31744u) * 256 + tid;
            int h = i & 1023, bt = i >> 10;
            int b = bt >> 7, t = bt & 127;
            int tk = (t == 0) ? 3 : outtok[b*128 + t - 1];
            g_demb[i] = dec_emb[(size_t)tk * 1024 + h];
        }
        return;
    }
    const float* in; float* out; int R, C, ld, col0; unsigned tile;
    if (id < 4096u)       { unsigned l4 = id >> 10; tile = id & 1023u;
                            in = enc_Whh + (size_t)l4*2048*512; out = g_WhhEncT + (size_t)l4*512*2048;
                            R = 2048; C = 512; ld = 512; col0 = 0; }
    else if (id < 8192u)  { tile = id - 4096u;  in = dec_Wih0;     out = g_WdecT0;
                            R = 4096; C = 1024; ld = 2048; col0 = 1024; }
    else if (id < 12288u) { tile = id - 8192u;  in = dec_Whh;      out = g_WdecT0 + (size_t)1024*4096;
                            R = 4096; C = 1024; ld = 1024; col0 = 0; }
    else if (id < 16384u) { tile = id - 12288u; in = dec_Wih_rest; out = g_WdecT1;
                            R = 4096; C = 1024; ld = 1024; col0 = 0; }
    else if (id < 20480u) { tile = id - 16384u; in = dec_Whh + (size_t)4096*1024; out = g_WdecT1 + (size_t)1024*4096;
                            R = 4096; C = 1024; ld = 1024; col0 = 0; }
    else if (id < 21504u) { tile = id - 20480u; in = linin_W;      out = g_lininT;
                            R = 1024; C = 1024; ld = 1024; col0 = 0; }
    else                  { tile = id - 21504u; in = linout_W;     out = g_linoutT;
                            R = 1024; C = 2048; ld = 2048; col0 = 0; }
    __shared__ float ts[32][33];
    int cbn = C >> 5;
    int cb = ((int)tile % cbn) << 5, rb = ((int)tile / cbn) << 5;
    int tx = tid & 31, ty = tid >> 5;
    #pragma unroll
    for (int i = 0; i < 32; i += 8)
        ts[ty + i][tx] = in[(size_t)(rb + ty + i) * ld + col0 + cb + tx];
    __syncthreads();
    #pragma unroll
    for (int i = 0; i < 32; i += 8)
        out[(size_t)(cb + ty + i) * R + rb + tx] = ts[tx][ty + i];
}

// ---------------- tiled GEMM tile ----------------
__device__ __forceinline__ void gemm128(
    const float* __restrict__ A, int lda,
    const float* __restrict__ W, int ldw,
    const float* __restrict__ bias,
    float* __restrict__ C, int ldc, int K, int mt, int nt) {
    __shared__ float As[16][132];
    __shared__ float Bs[16][132];
    int tid = threadIdx.x;
    int tx = tid & 15, ty = tid >> 4;
    size_t mb = (size_t)mt * 128, nb = (size_t)nt * 128;
    float2 acc[8][4];
    #pragma unroll
    for (int i = 0; i < 8; i++)
        #pragma unroll
        for (int j = 0; j < 4; j++) acc[i][j] = make_float2(0.f, 0.f);
    int lr = tid >> 2, lc4 = (tid & 3) * 4;
    const float* Ap  = A + (mb + lr) * (size_t)lda + lc4;
    const float* Ap2 = Ap + (size_t)64 * lda;
    const float* Wp  = W + (nb + lr) * (size_t)ldw + lc4;
    const float* Wp2 = Wp + (size_t)64 * ldw;
    for (int k0 = 0; k0 < K; k0 += 16) {
        float4 a0 = *(const float4*)(Ap  + k0);
        float4 a1 = *(const float4*)(Ap2 + k0);
        float4 b0 = *(const float4*)(Wp  + k0);
        float4 b1 = *(const float4*)(Wp2 + k0);
        As[lc4+0][lr] = a0.x; As[lc4+1][lr] = a0.y; As[lc4+2][lr] = a0.z; As[lc4+3][lr] = a0.w;
        As[lc4+0][lr+64] = a1.x; As[lc4+1][lr+64] = a1.y; As[lc4+2][lr+64] = a1.z; As[lc4+3][lr+64] = a1.w;
        Bs[lc4+0][lr] = b0.x; Bs[lc4+1][lr] = b0.y; Bs[lc4+2][lr] = b0.z; Bs[lc4+3][lr] = b0.w;
        Bs[lc4+0][lr+64] = b1.x; Bs[lc4+1][lr+64] = b1.y; Bs[lc4+2][lr+64] = b1.z; Bs[lc4+3][lr+64] = b1.w;
        __syncthreads();
        #pragma unroll
        for (int kk = 0; kk < 16; kk++) {
            float4 av0 = *(const float4*)&As[kk][ty*8];
            float4 av1 = *(const float4*)&As[kk][ty*8+4];
            float4 bv0 = *(const float4*)&Bs[kk][tx*8];
            float4 bv1 = *(const float4*)&Bs[kk][tx*8+4];
            float a8[8] = {av0.x,av0.y,av0.z,av0.w,av1.x,av1.y,av1.z,av1.w};
            float2 bp[4];
            bp[0] = make_float2(bv0.x, bv0.y); bp[1] = make_float2(bv0.z, bv0.w);
            bp[2] = make_float2(bv1.x, bv1.y); bp[3] = make_float2(bv1.z, bv1.w);
            #pragma unroll
            for (int i = 0; i < 8; i++) {
                float2 ai = make_float2(a8[i], a8[i]);
                #pragma unroll
                for (int j = 0; j < 4; j++) acc[i][j] = ffma2(ai, bp[j], acc[i][j]);
            }
        }
        __syncthreads();
    }
    float bsv[8];
    #pragma unroll
    for (int j = 0; j < 8; j++) bsv[j] = bias[nb + tx*8 + j];
    #pragma unroll
    for (int i = 0; i < 8; i++) {
        float* Cp = C + (mb + ty*8 + i) * (size_t)ldc + nb + tx*8;
        float4 o0, o1;
        o0.x = acc[i][0].x + bsv[0]; o0.y = acc[i][0].y + bsv[1];
        o0.z = acc[i][1].x + bsv[2]; o0.w = acc[i][1].y + bsv[3];
        o1.x = acc[i][2].x + bsv[4]; o1.y = acc[i][2].y + bsv[5];
        o1.z = acc[i][3].x + bsv[6]; o1.w = acc[i][3].y + bsv[7];
        *(float4*)Cp = o0;
        *(float4*)(Cp + 4) = o1;
    }
}

// launch 1: enc layer-0 gates (both dirs) + decoder preL0
__global__ void __launch_bounds__(256) k_gemmA(
    const float* __restrict__ enc_Wih, const float* __restrict__ enc_b,
    const float* __restrict__ dec_Wih0, const float* __restrict__ dec_b) {
    int id = blockIdx.x;
    if (id < 256)
        gemm128(g_xbuf0, 1024, enc_Wih, 1024, enc_b, g_gatesin, 2048, 1024, id >> 4, id & 15);
    else if (id < 512) {
        int j = id - 256;
        gemm128(g_xbuf0, 1024, enc_Wih + (size_t)2048*1024, 1024, enc_b + 2048,
                g_gatesin + (size_t)2048*2048, 2048, 1024, j >> 4, j & 15);
    } else {
        int j = id - 512;
        gemm128(g_demb, 1024, dec_Wih0, 2048, dec_b, g_preL0, 4096, 1024, j >> 5, j & 31);
    }
}

__global__ void __launch_bounds__(256) k_gemmGen(
    const float* __restrict__ gen_W, const float* __restrict__ gen_b,
    float* __restrict__ logits) {
    gemm128(g_opn, 1024, gen_W, 1024, gen_b, logits, 32000, 1024, blockIdx.y, blockIdx.x);
}

// ---------------- persistent encoder (both layers + mid-gates GEMM + encW) ----------------
__global__ void __launch_bounds__(256) k_encAll(
    const float* __restrict__ enc_Wih, const float* __restrict__ enc_b) {
    __shared__ float sbuf[1024];
    int tid = threadIdx.x, bid = blockIdx.x;
    int gi = bid * 256 + tid;

    for (int l = 0; l < 2; l++) {
        if (l == 1) {
            // layer-1 gates: 512 tiles, 4 per block, from xbuf1
            #pragma unroll 1
            for (int tt = 0; tt < 4; tt++) {
                int tile = bid * 4 + tt;
                int d = tile >> 8, j = tile & 255;
                gemm128(g_xbuf1, 1024, enc_Wih + (size_t)(2 + d)*2048*1024, 1024,
                        enc_b + (2 + d)*2048, g_gatesin + (size_t)d*2048*2048, 2048, 1024,
                        j >> 4, j & 15);
            }
            gridbar();
        }
        float* h = g_henc; float* c = g_cenc;
        if (gi < 2*16*512) { h[gi] = 0.f; c[gi] = 0.f; }
        gridbar();

        const float* WhhT = g_WhhEncT + (size_t)l*2*512*2048;
        float* xout = l ? g_xbuf0 : g_xbuf1;
        int d  = bid >> 6;
        int nc = (bid >> 3) & 7;
        int kc = bid & 7;
        int kbase = kc * 64;
        int n = nc * 256 + tid;
        const float* hv = h + d * 16 * 512;
        const float* wp = WhhT + (size_t)d * 512 * 2048 + (size_t)kbase * 2048 + n;
        float* pp = g_epart + (size_t)((d*8 + kc) * 16) * 2048 + n;

        for (int s = 0; s < 128; s++) {
            for (int i = tid; i < 64*16; i += 256) {
                int k = i >> 4, b = i & 15;
                sbuf[i] = hv[b*512 + kbase + k];
            }
            __syncthreads();
            {
                const float2* vs2 = (const float2*)sbuf;
                float2 acc[8];
                #pragma unroll
                for (int bp = 0; bp < 8; bp++) acc[bp] = make_float2(0.f, 0.f);
                #pragma unroll 8
                for (int k = 0; k < 64; k++) {
                    float w = wp[(size_t)k * 2048];
                    float2 w2 = make_float2(w, w);
                    #pragma unroll
                    for (int bp = 0; bp < 8; bp++) acc[bp] = ffma2(w2, vs2[k*8+bp], acc[bp]);
                }
                #pragma unroll
                for (int bp = 0; bp < 8; bp++) {
                    pp[(size_t)(2*bp)   * 2048] = acc[bp].x;
                    pp[(size_t)(2*bp+1) * 2048] = acc[bp].y;
                }
            }
            gridbar();
            if (gi < 16384) {
                int dd = gi >> 13, j = gi & 8191;
                int b = j >> 9, hh = j & 511;
                int sdir = dd ? (127 - s) : s;
                const float* gin = g_gatesin + ((size_t)dd*2048 + b*128 + sdir) * 2048;
                float g4[4];
                #pragma unroll
                for (int q4 = 0; q4 < 4; q4++) {
                    int nn = q4*512 + hh;
                    float v = gin[nn];
                    #pragma unroll
                    for (int k2 = 0; k2 < 8; k2++)
                        v += g_epart[(size_t)((dd*8 + k2)*16 + b)*2048 + nn];
                    g4[q4] = v;
                }
                int idx = (dd*16 + b)*512 + hh;
                float cn = sigf(g4[1]) * c[idx] + sigf(g4[0]) * tanhf(g4[2]);
                float hn = sigf(g4[3]) * tanhf(cn);
                c[idx] = cn; h[idx] = hn;
                xout[((size_t)b*128 + sdir)*1024 + dd*512 + hh] = hn;
            }
            gridbar();
        }
        if (gi < 16384) {
            int b = gi >> 10, hh = gi & 1023;
            float hv2, cv2;
            if (hh < 512) { hv2 = h[b*512 + hh];            cv2 = c[b*512 + hh]; }
            else          { hv2 = h[(16+b)*512 + hh - 512]; cv2 = c[(16+b)*512 + hh - 512]; }
            g_hdec[l*16*1024 + b*1024 + hh] = hv2;
            g_cdec[l*16*1024 + b*1024 + hh] = cv2;
        }
    }
    // encW = enc @ linin_W : one 128x128 tile per block (16 m-tiles x 8 n-tiles)
    gemm128(g_xbuf0, 1024, g_lininT, 1024, g_zero, g_encW, 1024, 1024, bid >> 3, bid & 7);
}

// ---------------- persistent decoder: 128 x 256 ----------------
__global__ void __launch_bounds__(256) k_dec_persist(
    const float* __restrict__ bias1, const float* __restrict__ enc) {
    __shared__ float sbuf[4096];
    int tid = threadIdx.x, bid = blockIdx.x;
    int gi = bid * 256 + tid;
    float* op = g_op;
    float* hd0 = g_hdec;            float* cd0 = g_cdec;
    float* hd1 = g_hdec + 16*1024;  float* cd1 = g_cdec + 16*1024;

    if (gi < 16*1024) op[gi] = 0.f;
    gridbar();

    int ncA = bid >> 3, kcA = bid & 7;
    int kbaseA = kcA * 256;
    int nA = ncA * 256 + tid;
    int ncG = bid >> 5, kcG = bid & 31;
    int kbaseG = kcG * 64;
    int nG = ncG * 256 + tid;

    for (int t = 0; t < 128; t++) {
        // Phase A: layer0 gate partials from [op, hd0]
        for (int i = tid; i < 256*16; i += 256) {
            int k = i >> 4, b = i & 15, kg = kbaseA + k;
            sbuf[i] = (kg < 1024) ? op[b*1024 + kg] : hd0[b*1024 + kg - 1024];
        }
        __syncthreads();
        {
            const float2* vs2 = (const float2*)sbuf;
            float2 acc[8];
            #pragma unroll
            for (int bp = 0; bp < 8; bp++) acc[bp] = make_float2(0.f, 0.f);
            const float* wp = g_WdecT0 + (size_t)kbaseA * 4096 + nA;
            #pragma unroll 8
            for (int k = 0; k < 256; k++) {
                float w = wp[(size_t)k * 4096];
                float2 w2 = make_float2(w, w);
                #pragma unroll
                for (int bp = 0; bp < 8; bp++) acc[bp] = ffma2(w2, vs2[k*8+bp], acc[bp]);
            }
            float* pp = g_part0 + (size_t)(kcA*16) * 4096 + nA;
            #pragma unroll
            for (int bp = 0; bp < 8; bp++) {
                pp[(size_t)(2*bp)   * 4096] = acc[bp].x;
                pp[(size_t)(2*bp+1) * 4096] = acc[bp].y;
            }
        }
        gridbar();
        // Phase B: cell0
        if (gi < 16384) {
            int b = gi >> 10, hh = gi & 1023;
            const float* pl = g_preL0 + ((size_t)b*128 + t) * 4096;
            float g4[4];
            #pragma unroll
            for (int q4 = 0; q4 < 4; q4++) {
                int n = q4*1024 + hh;
                float v = pl[n];
                #pragma unroll
                for (int k2 = 0; k2 < 8; k2++) v += g_part0[(size_t)(k2*16 + b)*4096 + n];
                g4[q4] = v;
            }
            int idx = b*1024 + hh;
            float cn = sigf(g4[1]) * cd0[idx] + sigf(g4[0]) * tanhf(g4[2]);
            float hn = sigf(g4[3]) * tanhf(cn);
            cd0[idx] = cn; hd0[idx] = hn;
        }
        gridbar();
        // Phase C: layer1 gate partials from [hd0, hd1]
        for (int i = tid; i < 256*16; i += 256) {
            int k = i >> 4, b = i & 15, kg = kbaseA + k;
            sbuf[i] = (kg < 1024) ? hd0[b*1024 + kg] : hd1[b*1024 + kg - 1024];
        }
        __syncthreads();
        {
            const float2* vs2 = (const float2*)sbuf;
            float2 acc[8];
            #pragma unroll
            for (int bp = 0; bp < 8; bp++) acc[bp] = make_float2(0.f, 0.f);
            const float* wp = g_WdecT1 + (size_t)kbaseA * 4096 + nA;
            #pragma unroll 8
            for (int k = 0; k < 256; k++) {
                float w = wp[(size_t)k * 4096];
                float2 w2 = make_float2(w, w);
                #pragma unroll
                for (int bp = 0; bp < 8; bp++) acc[bp] = ffma2(w2, vs2[k*8+bp], acc[bp]);
            }
            float* pp = g_part1 + (size_t)(kcA*16) * 4096 + nA;
            #pragma unroll
            for (int bp = 0; bp < 8; bp++) {
                pp[(size_t)(2*bp)   * 4096] = acc[bp].x;
                pp[(size_t)(2*bp+1) * 4096] = acc[bp].y;
            }
        }
        gridbar();
        // Phase D: cell1
        if (gi < 16384) {
            int b = gi >> 10, hh = gi & 1023;
            float g4[4];
            #pragma unroll
            for (int q4 = 0; q4 < 4; q4++) {
                int n = q4*1024 + hh;
                float v = bias1[n];
                #pragma unroll
                for (int k2 = 0; k2 < 8; k2++) v += g_part1[(size_t)(k2*16 + b)*4096 + n];
                g4[q4] = v;
            }
            int idx = b*1024 + hh;
            float cn = sigf(g4[1]) * cd1[idx] + sigf(g4[0]) * tanhf(g4[2]);
            float hn = sigf(g4[3]) * tanhf(cn);
            cd1[idx] = cn; hd1[idx] = hn;
        }
        gridbar();
        // Phase F1: scores via precomputed encW (all 128 blocks)
        {
            int b = bid >> 3, sg = bid & 7;
            for (int i = tid; i < 1024; i += 256) sbuf[i] = hd1[b*1024 + i];
            __syncthreads();
            int w = tid >> 5, lane = tid & 31;
            #pragma unroll
            for (int j2 = 0; j2 < 2; j2++) {
                int s = sg*16 + w*2 + j2;
                const float* er = g_encW + ((size_t)b*128 + s) * 1024;
                float a = 0.f;
                #pragma unroll 8
                for (int k = lane; k < 1024; k += 32) a += er[k] * sbuf[k];
                #pragma unroll
                for (int o = 16; o; o >>= 1) a += __shfl_xor_sync(0xffffffffu, a, o);
                if (!lane) g_scores[b*128 + s] = a;
            }
        }
        gridbar();
        // Phase F2: softmax + context (all 128 blocks; b = bid>>3, hseg = bid&7)
        {
            int b = bid >> 3, hseg = bid & 7;
            float* sc = sbuf;
            float* pc = sbuf + 128;
            if (tid < 128) sc[tid] = g_scores[b*128 + tid];
            __syncthreads();
            if (tid < 32) {
                float m = -1e30f;
                for (int s = tid; s < 128; s += 32) m = fmaxf(m, sc[s]);
                #pragma unroll
                for (int o = 16; o; o >>= 1) m = fmaxf(m, __shfl_xor_sync(0xffffffffu, m, o));
                float sum = 0.f;
                for (int s = tid; s < 128; s += 32) { float e2 = expf(sc[s]-m); sc[s] = e2; sum += e2; }
                #pragma unroll
                for (int o = 16; o; o >>= 1) sum += __shfl_xor_sync(0xffffffffu, sum, o);
                float inv = 1.f / sum;
                for (int s = tid; s < 128; s += 32) sc[s] *= inv;
            }
            __syncthreads();
            int h = hseg*128 + (tid & 127);
            int sh = tid >> 7;
            const float* e = enc + ((size_t)b*128 + sh*64) * 1024 + h;
            float a = 0.f;
            #pragma unroll 8
            for (int s = 0; s < 64; s++) a += sc[sh*64 + s] * e[(size_t)s*1024];
            pc[tid] = a;
            __syncthreads();
            if (tid < 128) g_cc[b*1024 + hseg*128 + tid] = pc[tid] + pc[tid + 128];
        }
        gridbar();
        // Phase G: linout partials from [cc, hd1]
        for (int i = tid; i < 64*16; i += 256) {
            int k = i >> 4, b = i & 15, kg = kbaseG + k;
            sbuf[i] = (kg < 1024) ? g_cc[b*1024 + kg] : hd1[b*1024 + kg - 1024];
        }
        __syncthreads();
        {
            const float2* vs2 = (const float2*)sbuf;
            float2 acc[8];
            #pragma unroll
            for (int bp = 0; bp < 8; bp++) acc[bp] = make_float2(0.f, 0.f);
            const float* wp = g_linoutT + (size_t)kbaseG * 1024 + nG;
            #pragma unroll 8
            for (int k = 0; k < 64; k++) {
                float w = wp[(size_t)k * 1024];
                float2 w2 = make_float2(w, w);
                #pragma unroll
                for (int bp = 0; bp < 8; bp++) acc[bp] = ffma2(w2, vs2[k*8+bp], acc[bp]);
            }
            float* pp = g_lopart + (size_t)(kcG*16) * 1024 + nG;
            #pragma unroll
            for (int bp = 0; bp < 8; bp++) {
                pp[(size_t)(2*bp)   * 1024] = acc[bp].x;
                pp[(size_t)(2*bp+1) * 1024] = acc[bp].y;
            }
        }
        gridbar();
        // Phase H: opn = tanh(sum)
        if (gi < 16384) {
            int b = gi >> 10, hh = gi & 1023;
            float v = 0.f;
            #pragma unroll
            for (int k2 = 0; k2 < 32; k2++) v += g_lopart[(size_t)(k2*16 + b)*1024 + hh];
            float o = tanhf(v);
            op[b*1024 + hh] = o;
            g_opn[((size_t)b*128 + t)*1024 + hh] = o;
        }
        gridbar();
    }
}

// ---------------- host ----------------
extern "C" void kernel_launch(void* const* d_in, const int* in_sizes, int n_in,
                              void* d_out, int out_size) {
    const float* enc_emb      = (const float*)d_in[0];
    const float* dec_emb      = (const float*)d_in[1];
    const float* enc_Wih      = (const float*)d_in[2];
    const float* enc_Whh      = (const float*)d_in[3];
    const float* enc_b        = (const float*)d_in[4];
    const float* dec_Wih0     = (const float*)d_in[5];
    const float* dec_Wih_rest = (const float*)d_in[6];
    const float* dec_Whh      = (const float*)d_in[7];
    const float* dec_b        = (const float*)d_in[8];
    const float* linin_W      = (const float*)d_in[9];
    const float* linout_W     = (const float*)d_in[10];
    const float* gen_W        = (const float*)d_in[11];
    const float* gen_b        = (const float*)d_in[12];
    const int*   inp          = (const int*)d_in[13];
    const int*   outtok       = (const int*)d_in[14];
    float* logits = (float*)d_out;

    void* p = nullptr;
    cudaGetSymbolAddress(&p, g_xbuf0);
    float* xbuf0 = (float*)p;

    // 0: prep
    k_prep<<<39936, 256>>>(enc_emb, dec_emb, enc_Whh, dec_Wih0, dec_Wih_rest,
                           dec_Whh, linin_W, linout_W, inp, outtok);
    // 1: enc layer-0 gates + preL0
    k_gemmA<<<1024, 256>>>(enc_Wih, enc_b, dec_Wih0, dec_b);
    // 2: encoder (both layers + mid GEMM + encW)
    k_encAll<<<128, 256>>>(enc_Wih, enc_b);
    // 3: decoder  (harness-profiled index)
    k_dec_persist<<<128, 256>>>(dec_b + 4096, xbuf0);
    // 4: generator
    k_gemmGen<<<dim3(250, 16), 256>>>(gen_W, gen_b, logits);
}

// round 12
// speedup vs baseline: 1.2959x; 1.0155x over previous
#include <cuda_runtime.h>
#include <cstdint>

#define NBLKu 128u

// ---------------- device scratch ----------------
__device__ float g_xbuf0[16*128*1024];
__device__ float g_xbuf1[16*128*1024];
__device__ float g_gatesin[2*2048*2048];
__device__ float g_WhhEncT[4*512*2048];
__device__ float g_epart[2*16*16*2048];
__device__ float g_hdec[2*16*1024];
__device__ float g_cdec[2*16*1024];
__device__ float g_hd0[16*1024];
__device__ float g_hd1[16*1024];
__device__ float g_demb[16*128*1024];
__device__ float g_preL0[2048*4096];
__device__ float g_WdecT0[2048*4096];
__device__ float g_WdecT1[2048*4096];
__device__ float g_lininT[1024*1024];
__device__ float g_linoutT[2048*1024];
__device__ float g_encW[2048*1024];
__device__ float g_zero[1024];
__device__ float g_op[16*1024];
__device__ float g_cc[16*1024];
__device__ float g_part0[128*4096];
__device__ float g_part1[128*4096];
__device__ float g_lopart[16*16*1024];
__device__ float g_opn[2048*1024];
__device__ unsigned g_barA, g_barG;

// ---------------- helpers ----------------
__device__ __forceinline__ float2 ffma2(float2 a, float2 b, float2 c) {
    unsigned long long ra = *reinterpret_cast<unsigned long long*>(&a);
    unsigned long long rb = *reinterpret_cast<unsigned long long*>(&b);
    unsigned long long rc = *reinterpret_cast<unsigned long long*>(&c);
    unsigned long long rd;
    asm("fma.rn.f32x2 %0, %1, %2, %3;" : "=l"(rd) : "l"(ra), "l"(rb), "l"(rc));
    return *reinterpret_cast<float2*>(&rd);
}
__device__ __forceinline__ float sigf(float x) { return 1.0f / (1.0f + expf(-x)); }
__device__ __forceinline__ float lstm_h(const float* g4, float& c) {
    float cn = sigf(g4[1]) * c + sigf(g4[0]) * tanhf(g4[2]);
    c = cn;
    return sigf(g4[3]) * tanhf(cn);
}

__device__ __forceinline__ void gridbar() {
    __syncthreads();
    if (threadIdx.x == 0) {
        unsigned gen;
        asm volatile("ld.volatile.global.u32 %0, [%1];" : "=r"(gen) : "l"(&g_barG));
        unsigned prev;
        asm volatile("atom.release.gpu.global.add.u32 %0, [%1], 1;"
                     : "=r"(prev) : "l"(&g_barA) : "memory");
        if (prev == NBLKu - 1u) {
            asm volatile("st.global.u32 [%0], 0;" :: "l"(&g_barA) : "memory");
            asm volatile("st.release.gpu.global.u32 [%0], %1;"
                         :: "l"(&g_barG), "r"(gen + 1u) : "memory");
        } else {
            unsigned cur;
            while (true) {
                asm volatile("ld.acquire.gpu.global.u32 %0, [%1];"
                             : "=r"(cur) : "l"(&g_barG) : "memory");
                if (cur != gen) break;
                __nanosleep(32);
            }
        }
    }
    __syncthreads();
}

// GEMV fragment: thread owns 4 n-cols x 2 batches. vs has stride-18 rows [k][b].
template<int NK>
__device__ __forceinline__ void gemv4x2(const float* __restrict__ wp, int ldw,
                                        const float* __restrict__ vs, int bp,
                                        float* __restrict__ pp, int ldp) {
    float2 a0 = make_float2(0.f,0.f), a1 = a0, a2 = a0, a3 = a0;
    #pragma unroll 8
    for (int k = 0; k < NK; k++) {
        float4 w4 = *(const float4*)(wp + (size_t)k * ldw);
        float2 bv = *(const float2*)(vs + k*18 + 2*bp);
        a0 = ffma2(make_float2(w4.x, w4.x), bv, a0);
        a1 = ffma2(make_float2(w4.y, w4.y), bv, a1);
        a2 = ffma2(make_float2(w4.z, w4.z), bv, a2);
        a3 = ffma2(make_float2(w4.w, w4.w), bv, a3);
    }
    *(float4*)pp         = make_float4(a0.x, a1.x, a2.x, a3.x);
    *(float4*)(pp + ldp) = make_float4(a0.y, a1.y, a2.y, a3.y);
}

// ---------------- prep: transposes + embeds ----------------
__global__ void __launch_bounds__(256) k_prep(
    const float* __restrict__ enc_emb, const float* __restrict__ dec_emb,
    const float* __restrict__ enc_Whh, const float* __restrict__ dec_Wih0,
    const float* __restrict__ dec_Wih_rest, const float* __restrict__ dec_Whh,
    const float* __restrict__ linin_W, const float* __restrict__ linout_W,
    const int* __restrict__ inp, const int* __restrict__ outtok) {
    unsigned id = blockIdx.x;
    int tid = threadIdx.x;
    if (id >= 23552u) {
        if (id < 31744u) {
            int i = (int)(id - 23552u) * 256 + tid;
            int h = i & 1023, tok = i >> 10;
            g_xbuf0[i] = enc_emb[(size_t)inp[tok] * 1024 + h];
        } else {
            int i = (int)(id - 31744u) * 256 + tid;
            int h = i & 1023, bt = i >> 10;
            int b = bt >> 7, t = bt & 127;
            int tk = (t == 0) ? 3 : outtok[b*128 + t - 1];
            g_demb[i] = dec_emb[(size_t)tk * 1024 + h];
        }
        return;
    }
    const float* in; float* out; int R, C, ld, col0; unsigned tile;
    if (id < 4096u)       { unsigned l4 = id >> 10; tile = id & 1023u;
                            in = enc_Whh + (size_t)l4*2048*512; out = g_WhhEncT + (size_t)l4*512*2048;
                            R = 2048; C = 512; ld = 512; col0 = 0; }
    else if (id < 8192u)  { tile = id - 4096u;  in = dec_Wih0;     out = g_WdecT0;
                            R = 4096; C = 1024; ld = 2048; col0 = 1024; }
    else if (id < 12288u) { tile = id - 8192u;  in = dec_Whh;      out = g_WdecT0 + (size_t)1024*4096;
                            R = 4096; C = 1024; ld = 1024; col0 = 0; }
    else if (id < 16384u) { tile = id - 12288u; in = dec_Wih_rest; out = g_WdecT1;
                            R = 4096; C = 1024; ld = 1024; col0 = 0; }
    else if (id < 20480u) { tile = id - 16384u; in = dec_Whh + (size_t)4096*1024; out = g_WdecT1 + (size_t)1024*4096;
                            R = 4096; C = 1024; ld = 1024; col0 = 0; }
    else if (id < 21504u) { tile = id - 20480u; in = linin_W;      out = g_lininT;
                            R = 1024; C = 1024; ld = 1024; col0 = 0; }
    else                  { tile = id - 21504u; in = linout_W;     out = g_linoutT;
                            R = 1024; C = 2048; ld = 2048; col0 = 0; }
    __shared__ float ts[32][33];
    int cbn = C >> 5;
    int cb = ((int)tile % cbn) << 5, rb = ((int)tile / cbn) << 5;
    int tx = tid & 31, ty = tid >> 5;
    #pragma unroll
    for (int i = 0; i < 32; i += 8)
        ts[ty + i][tx] = in[(size_t)(rb + ty + i) * ld + col0 + cb + tx];
    __syncthreads();
    #pragma unroll
    for (int i = 0; i < 32; i += 8)
        out[(size_t)(cb + ty + i) * R + rb + tx] = ts[tx][ty + i];
}

// ---------------- 512-thread GEMM tile: C = A@W^T + bias ----------------
__device__ __forceinline__ void gemm512(
    const float* __restrict__ A, int lda,
    const float* __restrict__ W, int ldw,
    const float* __restrict__ bias,
    float* __restrict__ C, int ldc, int K, int mt, int nt) {
    __shared__ float As[16][132];
    __shared__ float Bs[16][132];
    int tid = threadIdx.x;
    int tx = tid & 15, ty = tid >> 4;      // ty 0..31
    size_t mb = (size_t)mt * 128, nb = (size_t)nt * 128;
    float2 acc[4][4];
    #pragma unroll
    for (int i = 0; i < 4; i++)
        #pragma unroll
        for (int j = 0; j < 4; j++) acc[i][j] = make_float2(0.f, 0.f);
    int sr = tid >> 2, sk = (tid & 3) * 4;
    const float* Ap = A + (mb + sr) * (size_t)lda + sk;
    const float* Wp = W + (nb + sr) * (size_t)ldw + sk;
    for (int k0 = 0; k0 < K; k0 += 16) {
        float4 a = *(const float4*)(Ap + k0);
        float4 w = *(const float4*)(Wp + k0);
        As[sk+0][sr] = a.x; As[sk+1][sr] = a.y; As[sk+2][sr] = a.z; As[sk+3][sr] = a.w;
        Bs[sk+0][sr] = w.x; Bs[sk+1][sr] = w.y; Bs[sk+2][sr] = w.z; Bs[sk+3][sr] = w.w;
        __syncthreads();
        #pragma unroll
        for (int kk = 0; kk < 16; kk++) {
            float4 av  = *(const float4*)&As[kk][ty*4];
            float4 bv0 = *(const float4*)&Bs[kk][tx*8];
            float4 bv1 = *(const float4*)&Bs[kk][tx*8+4];
            float a4[4] = {av.x, av.y, av.z, av.w};
            float2 bpv[4];
            bpv[0] = make_float2(bv0.x, bv0.y); bpv[1] = make_float2(bv0.z, bv0.w);
            bpv[2] = make_float2(bv1.x, bv1.y); bpv[3] = make_float2(bv1.z, bv1.w);
            #pragma unroll
            for (int i = 0; i < 4; i++) {
                float2 ai = make_float2(a4[i], a4[i]);
                #pragma unroll
                for (int j = 0; j < 4; j++) acc[i][j] = ffma2(ai, bpv[j], acc[i][j]);
            }
        }
        __syncthreads();
    }
    float bs[8];
    #pragma unroll
    for (int j = 0; j < 8; j++) bs[j] = bias[nb + tx*8 + j];
    #pragma unroll
    for (int i = 0; i < 4; i++) {
        float* Cp = C + (mb + ty*4 + i) * (size_t)ldc + nb + tx*8;
        *(float4*)Cp       = make_float4(acc[i][0].x + bs[0], acc[i][0].y + bs[1],
                                         acc[i][1].x + bs[2], acc[i][1].y + bs[3]);
        *(float4*)(Cp + 4) = make_float4(acc[i][2].x + bs[4], acc[i][2].y + bs[5],
                                         acc[i][3].x + bs[6], acc[i][3].y + bs[7]);
    }
}

__global__ void __launch_bounds__(512, 2) k_gemmA(
    const float* __restrict__ enc_Wih, const float* __restrict__ enc_b,
    const float* __restrict__ dec_Wih0, const float* __restrict__ dec_b) {
    int id = blockIdx.x;
    if (id < 256)
        gemm512(g_xbuf0, 1024, enc_Wih, 1024, enc_b, g_gatesin, 2048, 1024, id >> 4, id & 15);
    else if (id < 512) {
        int j = id - 256;
        gemm512(g_xbuf0, 1024, enc_Wih + (size_t)2048*1024, 1024, enc_b + 2048,
                g_gatesin + (size_t)2048*2048, 2048, 1024, j >> 4, j & 15);
    } else {
        int j = id - 512;
        gemm512(g_demb, 1024, dec_Wih0, 2048, dec_b, g_preL0, 4096, 1024, j >> 5, j & 31);
    }
}

__global__ void __launch_bounds__(512, 2) k_gemmGen(
    const float* __restrict__ gen_W, const float* __restrict__ gen_b,
    float* __restrict__ logits) {
    gemm512(g_opn, 1024, gen_W, 1024, gen_b, logits, 32000, 1024, blockIdx.y, blockIdx.x);
}

// ---------------- persistent encoder: 128 x 512 ----------------
__global__ void __launch_bounds__(512, 1) k_encAll(
    const float* __restrict__ enc_Wih, const float* __restrict__ enc_b) {
    __shared__ float sb[4608];
    int tid = threadIdx.x, bid = blockIdx.x;
    int d = bid >> 6, nc = (bid >> 3) & 7, kc = bid & 7;
    int bp = tid & 7, ng = tid >> 3;
    int n4 = nc*256 + ng*4;

    for (int l = 0; l < 2; l++) {
        if (l == 1) {
            gridbar();   // xbuf1 complete
            #pragma unroll 1
            for (int tt = 0; tt < 4; tt++) {
                int tile = bid*4 + tt;
                int d2 = tile >> 8, j = tile & 255;
                gemm512(g_xbuf1, 1024, enc_Wih + (size_t)(2 + d2)*2048*1024, 1024,
                        enc_b + (2 + d2)*2048, g_gatesin + (size_t)d2*2048*2048, 2048, 1024,
                        j >> 4, j & 15);
            }
            gridbar();
        }
        const float* WhhT = g_WhhEncT + (size_t)(l*2 + d)*512*2048;
        const float* gin  = g_gatesin + (size_t)d*2048*2048;
        float* xout = l ? g_xbuf0 : g_xbuf1;
        float creg[2] = {0.f, 0.f};

        for (int s = 0; s <= 128; s++) {
            #pragma unroll
            for (int j = 0; j < 2; j++) {
                int i2 = tid + 512*j;
                int b = i2 >> 6, k = i2 & 63;
                int hh = kc*64 + k;
                float v;
                if (s == 0) { v = 0.f; creg[j] = 0.f; }
                else {
                    int sp = s - 1;
                    int sdir = d ? (127 - sp) : sp;
                    const float* gr = gin + ((size_t)b*128 + sdir)*2048;
                    const float* ep = g_epart + (size_t)(sp & 1)*524288 + (size_t)(d*8)*16*2048;
                    float g4[4];
                    #pragma unroll
                    for (int q = 0; q < 4; q++) {
                        int col = q*512 + hh;
                        float x = gr[col];
                        #pragma unroll
                        for (int p = 0; p < 8; p++) x += ep[(size_t)(p*16 + b)*2048 + col];
                        g4[q] = x;
                    }
                    v = lstm_h(g4, creg[j]);
                    if (nc == 0) {
                        xout[((size_t)b*128 + sdir)*1024 + d*512 + hh] = v;
                        if (s == 128) {
                            g_hdec[l*16384 + b*1024 + d*512 + hh] = v;
                            g_cdec[l*16384 + b*1024 + d*512 + hh] = creg[j];
                        }
                    }
                }
                if (s < 128) sb[k*18 + b] = v;
            }
            if (s == 128) break;
            __syncthreads();
            gemv4x2<64>(WhhT + (size_t)(kc*64)*2048 + n4, 2048, sb, bp,
                        g_epart + (size_t)(s & 1)*524288 + (size_t)((d*8 + kc)*16 + 2*bp)*2048 + n4,
                        2048);
            gridbar();
        }
    }
    gridbar();   // xbuf0 (enc output) complete
    gemm512(g_xbuf0, 1024, g_lininT, 1024, g_zero, g_encW, 1024, 1024, bid >> 3, bid & 7);
}

// ---------------- persistent decoder: 128 x 512, 5 phases/step ----------------
__global__ void __launch_bounds__(512, 1) k_dec_persist(const float* __restrict__ bias1) {
    __shared__ float sb[4608];
    int tid = threadIdx.x, bid = blockIdx.x;
    int kcA = bid & 7, ncA = bid >> 3;
    int kcG = bid & 15, ncG = bid >> 4;
    int bF = bid >> 3, sg = bid & 7;
    int bp = tid & 7, ng = tid >> 3;
    int n4 = ncA*256 + ng*4;
    int n2 = ncG*128 + ng*2;

    float cd0[8];
    if (kcA < 4) {
        #pragma unroll
        for (int j = 0; j < 8; j++) {
            int i2 = tid + 512*j;
            int b = i2 >> 8, k = i2 & 255;
            cd0[j] = g_cdec[b*1024 + kcA*256 + k];
        }
    }
    float cd1f[2];
    cd1f[0] = g_cdec[16384 + bF*1024 + tid];
    cd1f[1] = g_cdec[16384 + bF*1024 + tid + 512];

    for (int t = 0; t < 128; t++) {
        // ---- Phase A: stage [op(t-1) ; hd0(t-1)] -> part0 ----
        #pragma unroll
        for (int j = 0; j < 8; j++) {
            int i2 = tid + 512*j;
            int b = i2 >> 8, k = i2 & 255;
            int kg = kcA*256 + k;
            float v;
            if (kcA < 4) v = t ? g_op[b*1024 + kg] : 0.f;
            else {
                int hh = kg - 1024;
                v = t ? g_hd0[b*1024 + hh] : g_hdec[b*1024 + hh];
            }
            sb[k*18 + b] = v;
        }
        __syncthreads();
        gemv4x2<256>(g_WdecT0 + (size_t)(kcA*256)*4096 + n4, 4096, sb, bp,
                     g_part0 + (size_t)(kcA*16 + 2*bp)*4096 + n4, 4096);
        gridbar();
        // ---- Phase C: stage [cell0(t) ; hd1(t-1)] -> part1 ----
        #pragma unroll
        for (int j = 0; j < 8; j++) {
            int i2 = tid + 512*j;
            int b = i2 >> 8, k = i2 & 255;
            int kg = kcA*256 + k;
            float v;
            if (kcA < 4) {
                const float* pl = g_preL0 + ((size_t)b*128 + t)*4096;
                float g4[4];
                #pragma unroll
                for (int q = 0; q < 4; q++) {
                    int col = q*1024 + kg;
                    float x = pl[col];
                    #pragma unroll
                    for (int p = 0; p < 8; p++) x += g_part0[(size_t)(p*16 + b)*4096 + col];
                    g4[q] = x;
                }
                v = lstm_h(g4, cd0[j]);
                if (ncA == 0) g_hd0[b*1024 + kg] = v;
            } else {
                int hh = kg - 1024;
                v = t ? g_hd1[b*1024 + hh] : g_hdec[16384 + b*1024 + hh];
            }
            sb[k*18 + b] = v;
        }
        __syncthreads();
        gemv4x2<256>(g_WdecT1 + (size_t)(kcA*256)*4096 + n4, 4096, sb, bp,
                     g_part1 + (size_t)(kcA*16 + 2*bp)*4096 + n4, 4096);
        gridbar();
        // ---- Phase F: cell1(t) -> hd1, scores, softmax, context ----
        #pragma unroll
        for (int j = 0; j < 2; j++) {
            int hh = tid + 512*j;
            float g4[4];
            #pragma unroll
            for (int q = 0; q < 4; q++) {
                int col = q*1024 + hh;
                float x = bias1[col];
                #pragma unroll
                for (int p = 0; p < 8; p++) x += g_part1[(size_t)(p*16 + bF)*4096 + col];
                g4[q] = x;
            }
            float v = lstm_h(g4, cd1f[j]);
            sb[hh] = v;
            if (sg == 0) g_hd1[bF*1024 + hh] = v;
        }
        __syncthreads();
        {
            int w = tid >> 5, lane = tid & 31;
            float* sc = sb + 1024;
            #pragma unroll 1
            for (int j2 = 0; j2 < 8; j2++) {
                int s = w*8 + j2;
                const float* er = g_encW + ((size_t)bF*128 + s)*1024;
                float a = 0.f;
                #pragma unroll 8
                for (int k = lane; k < 1024; k += 32) a += er[k] * sb[k];
                #pragma unroll
                for (int o = 16; o; o >>= 1) a += __shfl_xor_sync(0xffffffffu, a, o);
                if (!lane) sc[s] = a;
            }
        }
        __syncthreads();
        if (tid < 32) {
            float* sc = sb + 1024;
            float m = -1e30f;
            #pragma unroll
            for (int s = tid; s < 128; s += 32) m = fmaxf(m, sc[s]);
            #pragma unroll
            for (int o = 16; o; o >>= 1) m = fmaxf(m, __shfl_xor_sync(0xffffffffu, m, o));
            float sum = 0.f;
            #pragma unroll
            for (int s = tid; s < 128; s += 32) { float e2 = expf(sc[s]-m); sc[s] = e2; sum += e2; }
            #pragma unroll
            for (int o = 16; o; o >>= 1) sum += __shfl_xor_sync(0xffffffffu, sum, o);
            float inv = 1.f / sum;
            #pragma unroll
            for (int s = tid; s < 128; s += 32) sc[s] *= inv;
        }
        __syncthreads();
        {
            const float* sc = sb + 1024;
            float* pc = sb + 1152;
            int hoff = tid & 127, squad = tid >> 7;
            int h = sg*128 + hoff;
            const float* e = g_xbuf0 + ((size_t)bF*128 + squad*32)*1024 + h;
            float a = 0.f;
            #pragma unroll 8
            for (int s = 0; s < 32; s++) a += sc[squad*32 + s] * e[(size_t)s*1024];
            pc[tid] = a;
            __syncthreads();
            if (tid < 128)
                g_cc[bF*1024 + sg*128 + tid] = pc[tid] + pc[tid+128] + pc[tid+256] + pc[tid+384];
        }
        gridbar();
        // ---- Phase G: linout partials from [cc ; hd1] ----
        #pragma unroll
        for (int j = 0; j < 4; j++) {
            int i2 = tid + 512*j;
            int b = i2 >> 7, k = i2 & 127;
            int kg = kcG*128 + k;
            sb[k*18 + b] = (kg < 1024) ? g_cc[b*1024 + kg] : g_hd1[b*1024 + kg - 1024];
        }
        __syncthreads();
        {
            float2 a0 = make_float2(0.f,0.f), a1 = a0;
            const float* wp = g_linoutT + (size_t)(kcG*128)*1024 + n2;
            #pragma unroll 8
            for (int k = 0; k < 128; k++) {
                float2 w2 = *(const float2*)(wp + (size_t)k*1024);
                float2 bv = *(const float2*)&sb[k*18 + 2*bp];
                a0 = ffma2(make_float2(w2.x, w2.x), bv, a0);
                a1 = ffma2(make_float2(w2.y, w2.y), bv, a1);
            }
            float* pp = g_lopart + (size_t)(kcG*16 + 2*bp)*1024 + n2;
            pp[0] = a0.x; pp[1] = a1.x;
            pp[1024] = a0.y; pp[1025] = a1.y;
        }
        gridbar();
        // ---- Phase H: opn = tanh(sum), op ----
        if (tid < 128) {
            int gi2 = bid*128 + tid;
            int b = gi2 >> 10, hh = gi2 & 1023;
            float v = 0.f;
            #pragma unroll
            for (int p = 0; p < 16; p++) v += g_lopart[(size_t)(p*16 + b)*1024 + hh];
            float o = tanhf(v);
            g_op[b*1024 + hh] = o;
            g_opn[((size_t)b*128 + t)*1024 + hh] = o;
        }
        gridbar();
    }
}

// ---------------- host ----------------
extern "C" void kernel_launch(void* const* d_in, const int* in_sizes, int n_in,
                              void* d_out, int out_size) {
    const float* enc_emb      = (const float*)d_in[0];
    const float* dec_emb      = (const float*)d_in[1];
    const float* enc_Wih      = (const float*)d_in[2];
    const float* enc_Whh      = (const float*)d_in[3];
    const float* enc_b        = (const float*)d_in[4];
    const float* dec_Wih0     = (const float*)d_in[5];
    const float* dec_Wih_rest = (const float*)d_in[6];
    const float* dec_Whh      = (const float*)d_in[7];
    const float* dec_b        = (const float*)d_in[8];
    const float* linin_W      = (const float*)d_in[9];
    const float* linout_W     = (const float*)d_in[10];
    const float* gen_W        = (const float*)d_in[11];
    const float* gen_b        = (const float*)d_in[12];
    const int*   inp          = (const int*)d_in[13];
    const int*   outtok       = (const int*)d_in[14];
    float* logits = (float*)d_out;

    // 0: prep
    k_prep<<<39936, 256>>>(enc_emb, dec_emb, enc_Whh, dec_Wih0, dec_Wih_rest,
                           dec_Whh, linin_W, linout_W, inp, outtok);
    // 1: enc layer-0 gates + preL0
    k_gemmA<<<1024, 512>>>(enc_Wih, enc_b, dec_Wih0, dec_b);
    // 2: encoder (both layers + L1 gates + encW)
    k_encAll<<<128, 512>>>(enc_Wih, enc_b);
    // 3: decoder (profiled index)
    k_dec_persist<<<128, 512>>>(dec_b + 4096);
    // 4: generator
    k_gemmGen<<<dim3(250, 16), 512>>>(gen_W, gen_b, logits);
}

// round 14
// speedup vs baseline: 1.4881x; 1.1483x over previous
#include <cuda_runtime.h>
#include <cstdint>

#define NBLKu 128u

// ---------------- device scratch ----------------
__device__ float g_xbuf0[16*128*1024];
__device__ float g_xbuf1[16*128*1024];
__device__ float g_gatesin[2*2048*2048];
__device__ float g_WhhEncT[4*512*2048];
__device__ float g_epart[2*16*16*2048];
__device__ float g_hdec[2*16*1024];
__device__ float g_cdec[2*16*1024];
__device__ float g_hd0[16*1024];
__device__ float g_hd1[16*1024];
__device__ float g_demb[16*128*1024];
__device__ float g_preL0[2048*4096];
__device__ float g_WdecT0[2048*4096];
__device__ float g_WdecT1[2048*4096];
__device__ float g_lininT[1024*1024];
__device__ float g_linoutT[2048*1024];
__device__ float g_encW[2048*1024];
__device__ float g_zero[1024];
__device__ float g_op[16*1024];
__device__ float g_cc[16*1024];
__device__ float g_part0[128*4096];
__device__ float g_part1[128*4096];
__device__ float g_lopart[16*16*1024];
__device__ float g_opn[2048*1024];
__device__ unsigned g_barA, g_barG;

// ---------------- helpers ----------------
__device__ __forceinline__ float2 ffma2(float2 a, float2 b, float2 c) {
    unsigned long long ra = *reinterpret_cast<unsigned long long*>(&a);
    unsigned long long rb = *reinterpret_cast<unsigned long long*>(&b);
    unsigned long long rc = *reinterpret_cast<unsigned long long*>(&c);
    unsigned long long rd;
    asm("fma.rn.f32x2 %0, %1, %2, %3;" : "=l"(rd) : "l"(ra), "l"(rb), "l"(rc));
    return *reinterpret_cast<float2*>(&rd);
}
__device__ __forceinline__ float sigf(float x) { return 1.0f / (1.0f + expf(-x)); }
__device__ __forceinline__ float lstm_h(const float* g4, float& c) {
    float cn = sigf(g4[1]) * c + sigf(g4[0]) * tanhf(g4[2]);
    c = cn;
    return sigf(g4[3]) * tanhf(cn);
}
__device__ __forceinline__ unsigned cvt_tf32(float x) {
    unsigned r; asm("cvt.rna.tf32.f32 %0, %1;" : "=r"(r) : "f"(x)); return r;
}
__device__ __forceinline__ void mma_tf32(float* d, const unsigned* a, const unsigned* b) {
    asm("mma.sync.aligned.m16n8k8.row.col.f32.tf32.tf32.f32 "
        "{%0,%1,%2,%3}, {%4,%5,%6,%7}, {%8,%9}, {%0,%1,%2,%3};"
        : "+f"(d[0]), "+f"(d[1]), "+f"(d[2]), "+f"(d[3])
        : "r"(a[0]), "r"(a[1]), "r"(a[2]), "r"(a[3]), "r"(b[0]), "r"(b[1]));
}

__device__ __forceinline__ void gridbar() {
    __syncthreads();
    if (threadIdx.x == 0) {
        unsigned gen;
        asm volatile("ld.volatile.global.u32 %0, [%1];" : "=r"(gen) : "l"(&g_barG));
        unsigned prev;
        asm volatile("atom.release.gpu.global.add.u32 %0, [%1], 1;"
                     : "=r"(prev) : "l"(&g_barA) : "memory");
        if (prev == NBLKu - 1u) {
            asm volatile("st.global.u32 [%0], 0;" :: "l"(&g_barA) : "memory");
            asm volatile("st.release.gpu.global.u32 [%0], %1;"
                         :: "l"(&g_barG), "r"(gen + 1u) : "memory");
        } else {
            unsigned cur;
            while (true) {
                asm volatile("ld.acquire.gpu.global.u32 %0, [%1];"
                             : "=r"(cur) : "l"(&g_barG) : "memory");
                if (cur != gen) break;
                __nanosleep(32);
            }
        }
    }
    __syncthreads();
}

// GEMV fragment: thread owns 4 n-cols x 2 batches. vs has stride-18 rows [k][b].
template<int NK>
__device__ __forceinline__ void gemv4x2(const float* __restrict__ wp, int ldw,
                                        const float* __restrict__ vs, int bp,
                                        float* __restrict__ pp, int ldp) {
    float2 a0 = make_float2(0.f,0.f), a1 = a0, a2 = a0, a3 = a0;
    #pragma unroll 8
    for (int k = 0; k < NK; k++) {
        float4 w4 = *(const float4*)(wp + (size_t)k * ldw);
        float2 bv = *(const float2*)(vs + k*18 + 2*bp);
        a0 = ffma2(make_float2(w4.x, w4.x), bv, a0);
        a1 = ffma2(make_float2(w4.y, w4.y), bv, a1);
        a2 = ffma2(make_float2(w4.z, w4.z), bv, a2);
        a3 = ffma2(make_float2(w4.w, w4.w), bv, a3);
    }
    *(float4*)pp         = make_float4(a0.x, a1.x, a2.x, a3.x);
    *(float4*)(pp + ldp) = make_float4(a0.y, a1.y, a2.y, a3.y);
}

// ---------------- prep: transposes + embeds ----------------
__global__ void __launch_bounds__(256) k_prep(
    const float* __restrict__ enc_emb, const float* __restrict__ dec_emb,
    const float* __restrict__ enc_Whh, const float* __restrict__ dec_Wih0,
    const float* __restrict__ dec_Wih_rest, const float* __restrict__ dec_Whh,
    const float* __restrict__ linin_W, const float* __restrict__ linout_W,
    const int* __restrict__ inp, const int* __restrict__ outtok) {
    unsigned id = blockIdx.x;
    int tid = threadIdx.x;
    if (id >= 23552u) {
        if (id < 31744u) {
            int i = (int)(id - 23552u) * 256 + tid;
            int h = i & 1023, tok = i >> 10;
            g_xbuf0[i] = enc_emb[(size_t)inp[tok] * 1024 + h];
        } else {
            int i = (int)(id - 31744u) * 256 + tid;
            int h = i & 1023, bt = i >> 10;
            int b = bt >> 7, t = bt & 127;
            int tk = (t == 0) ? 3 : outtok[b*128 + t - 1];
            g_demb[i] = dec_emb[(size_t)tk * 1024 + h];
        }
        return;
    }
    const float* in; float* out; int R, C, ld, col0; unsigned tile;
    if (id < 4096u)       { unsigned l4 = id >> 10; tile = id & 1023u;
                            in = enc_Whh + (size_t)l4*2048*512; out = g_WhhEncT + (size_t)l4*512*2048;
                            R = 2048; C = 512; ld = 512; col0 = 0; }
    else if (id < 8192u)  { tile = id - 4096u;  in = dec_Wih0;     out = g_WdecT0;
                            R = 4096; C = 1024; ld = 2048; col0 = 1024; }
    else if (id < 12288u) { tile = id - 8192u;  in = dec_Whh;      out = g_WdecT0 + (size_t)1024*4096;
                            R = 4096; C = 1024; ld = 1024; col0 = 0; }
    else if (id < 16384u) { tile = id - 12288u; in = dec_Wih_rest; out = g_WdecT1;
                            R = 4096; C = 1024; ld = 1024; col0 = 0; }
    else if (id < 20480u) { tile = id - 16384u; in = dec_Whh + (size_t)4096*1024; out = g_WdecT1 + (size_t)1024*4096;
                            R = 4096; C = 1024; ld = 1024; col0 = 0; }
    else if (id < 21504u) { tile = id - 20480u; in = linin_W;      out = g_lininT;
                            R = 1024; C = 1024; ld = 1024; col0 = 0; }
    else                  { tile = id - 21504u; in = linout_W;     out = g_linoutT;
                            R = 1024; C = 2048; ld = 2048; col0 = 0; }
    __shared__ float ts[32][33];
    int cbn = C >> 5;
    int cb = ((int)tile % cbn) << 5, rb = ((int)tile / cbn) << 5;
    int tx = tid & 31, ty = tid >> 5;
    #pragma unroll
    for (int i = 0; i < 32; i += 8)
        ts[ty + i][tx] = in[(size_t)(rb + ty + i) * ld + col0 + cb + tx];
    __syncthreads();
    #pragma unroll
    for (int i = 0; i < 32; i += 8)
        out[(size_t)(cb + ty + i) * R + rb + tx] = ts[tx][ty + i];
}

// ---------------- 512-thread fp32 GEMM tile ----------------
__device__ __forceinline__ void gemm512(
    const float* __restrict__ A, int lda,
    const float* __restrict__ W, int ldw,
    const float* __restrict__ bias,
    float* __restrict__ C, int ldc, int K, int mt, int nt) {
    __shared__ float As[16][132];
    __shared__ float Bs[16][132];
    int tid = threadIdx.x;
    int tx = tid & 15, ty = tid >> 4;
    size_t mb = (size_t)mt * 128, nb = (size_t)nt * 128;
    float2 acc[4][4];
    #pragma unroll
    for (int i = 0; i < 4; i++)
        #pragma unroll
        for (int j = 0; j < 4; j++) acc[i][j] = make_float2(0.f, 0.f);
    int sr = tid >> 2, sk = (tid & 3) * 4;
    const float* Ap = A + (mb + sr) * (size_t)lda + sk;
    const float* Wp = W + (nb + sr) * (size_t)ldw + sk;
    for (int k0 = 0; k0 < K; k0 += 16) {
        float4 a = *(const float4*)(Ap + k0);
        float4 w = *(const float4*)(Wp + k0);
        As[sk+0][sr] = a.x; As[sk+1][sr] = a.y; As[sk+2][sr] = a.z; As[sk+3][sr] = a.w;
        Bs[sk+0][sr] = w.x; Bs[sk+1][sr] = w.y; Bs[sk+2][sr] = w.z; Bs[sk+3][sr] = w.w;
        __syncthreads();
        #pragma unroll
        for (int kk = 0; kk < 16; kk++) {
            float4 av  = *(const float4*)&As[kk][ty*4];
            float4 bv0 = *(const float4*)&Bs[kk][tx*8];
            float4 bv1 = *(const float4*)&Bs[kk][tx*8+4];
            float a4[4] = {av.x, av.y, av.z, av.w};
            float2 bpv[4];
            bpv[0] = make_float2(bv0.x, bv0.y); bpv[1] = make_float2(bv0.z, bv0.w);
            bpv[2] = make_float2(bv1.x, bv1.y); bpv[3] = make_float2(bv1.z, bv1.w);
            #pragma unroll
            for (int i = 0; i < 4; i++) {
                float2 ai = make_float2(a4[i], a4[i]);
                #pragma unroll
                for (int j = 0; j < 4; j++) acc[i][j] = ffma2(ai, bpv[j], acc[i][j]);
            }
        }
        __syncthreads();
    }
    float bs[8];
    #pragma unroll
    for (int j = 0; j < 8; j++) bs[j] = bias[nb + tx*8 + j];
    #pragma unroll
    for (int i = 0; i < 4; i++) {
        float* Cp = C + (mb + ty*4 + i) * (size_t)ldc + nb + tx*8;
        *(float4*)Cp       = make_float4(acc[i][0].x + bs[0], acc[i][0].y + bs[1],
                                         acc[i][1].x + bs[2], acc[i][1].y + bs[3]);
        *(float4*)(Cp + 4) = make_float4(acc[i][2].x + bs[4], acc[i][2].y + bs[5],
                                         acc[i][3].x + bs[6], acc[i][3].y + bs[7]);
    }
}

// ---------------- 512-thread tf32 tensor-core GEMM tile ----------------
// C[128 x 128] = A[128,K] @ W[128,K]^T + bias. 16 warps, warp tile 32x32.
__device__ __forceinline__ void gemm_mma512(
    const float* __restrict__ A, int lda,
    const float* __restrict__ W, int ldw,
    const float* __restrict__ bias,
    float* __restrict__ C, int ldc, int K, int mt, int nt) {
    __shared__ unsigned Asm[16][132];   // [k][m]
    __shared__ unsigned Wsm[16][132];   // [k][n]
    int tid = threadIdx.x;
    int wid = tid >> 5, lane = tid & 31;
    int wm = (wid & 3) * 32, wn = (wid >> 2) * 32;
    int qrow = lane >> 2, qk = lane & 3;
    size_t mb = (size_t)mt * 128, nb = (size_t)nt * 128;
    float acc[2][4][4];
    #pragma unroll
    for (int i = 0; i < 2; i++)
        #pragma unroll
        for (int j = 0; j < 4; j++)
            #pragma unroll
            for (int q = 0; q < 4; q++) acc[i][j][q] = 0.f;
    int sr = tid >> 2, sk = (tid & 3) * 4;
    const float* Ap = A + (mb + sr) * (size_t)lda + sk;
    const float* Wp = W + (nb + sr) * (size_t)ldw + sk;
    float4 a = *(const float4*)Ap;
    float4 w = *(const float4*)Wp;
    for (int k0 = 0; k0 < K; k0 += 16) {
        Asm[sk+0][sr] = cvt_tf32(a.x); Asm[sk+1][sr] = cvt_tf32(a.y);
        Asm[sk+2][sr] = cvt_tf32(a.z); Asm[sk+3][sr] = cvt_tf32(a.w);
        Wsm[sk+0][sr] = cvt_tf32(w.x); Wsm[sk+1][sr] = cvt_tf32(w.y);
        Wsm[sk+2][sr] = cvt_tf32(w.z); Wsm[sk+3][sr] = cvt_tf32(w.w);
        __syncthreads();
        if (k0 + 16 < K) {
            a = *(const float4*)(Ap + k0 + 16);
            w = *(const float4*)(Wp + k0 + 16);
        }
        #pragma unroll
        for (int kk = 0; kk < 16; kk += 8) {
            unsigned af[2][4], bf[4][2];
            #pragma unroll
            for (int i = 0; i < 2; i++) {
                int m0 = wm + i*16 + qrow;
                af[i][0] = Asm[kk+qk][m0];
                af[i][1] = Asm[kk+qk][m0+8];
                af[i][2] = Asm[kk+qk+4][m0];
                af[i][3] = Asm[kk+qk+4][m0+8];
            }
            #pragma unroll
            for (int j = 0; j < 4; j++) {
                int n0 = wn + j*8 + qrow;
                bf[j][0] = Wsm[kk+qk][n0];
                bf[j][1] = Wsm[kk+qk+4][n0];
            }
            #pragma unroll
            for (int i = 0; i < 2; i++)
                #pragma unroll
                for (int j = 0; j < 4; j++) mma_tf32(acc[i][j], af[i], bf[j]);
        }
        __syncthreads();
    }
    #pragma unroll
    for (int i = 0; i < 2; i++) {
        #pragma unroll
        for (int j = 0; j < 4; j++) {
            size_t r0 = mb + wm + i*16 + qrow;
            size_t c0 = nb + wn + j*8 + qk*2;
            float2 bv = *(const float2*)(bias + c0);
            *(float2*)(C + r0 * (size_t)ldc + c0) =
                make_float2(acc[i][j][0] + bv.x, acc[i][j][1] + bv.y);
            *(float2*)(C + (r0 + 8) * (size_t)ldc + c0) =
                make_float2(acc[i][j][2] + bv.x, acc[i][j][3] + bv.y);
        }
    }
}

__global__ void __launch_bounds__(512, 2) k_gemmA(
    const float* __restrict__ enc_Wih, const float* __restrict__ enc_b,
    const float* __restrict__ dec_Wih0, const float* __restrict__ dec_b) {
    int id = blockIdx.x;
    if (id < 256)
        gemm512(g_xbuf0, 1024, enc_Wih, 1024, enc_b, g_gatesin, 2048, 1024, id >> 4, id & 15);
    else if (id < 512) {
        int j = id - 256;
        gemm512(g_xbuf0, 1024, enc_Wih + (size_t)2048*1024, 1024, enc_b + 2048,
                g_gatesin + (size_t)2048*2048, 2048, 1024, j >> 4, j & 15);
    } else {
        int j = id - 512;
        gemm_mma512(g_demb, 1024, dec_Wih0, 2048, dec_b, g_preL0, 4096, 1024, j >> 5, j & 31);
    }
}

__global__ void __launch_bounds__(512, 2) k_gemmGen(
    const float* __restrict__ gen_W, const float* __restrict__ gen_b,
    float* __restrict__ logits) {
    gemm_mma512(g_opn, 1024, gen_W, 1024, gen_b, logits, 32000, 1024, blockIdx.y, blockIdx.x);
}

// ---------------- persistent encoder: 128 x 512 ----------------
__global__ void __launch_bounds__(512, 1) k_encAll(
    const float* __restrict__ enc_Wih, const float* __restrict__ enc_b) {
    __shared__ float sb[4608];
    int tid = threadIdx.x, bid = blockIdx.x;
    int d = bid >> 6, nc = (bid >> 3) & 7, kc = bid & 7;
    int bp = tid & 7, ng = tid >> 3;
    int n4 = nc*256 + ng*4;

    for (int l = 0; l < 2; l++) {
        if (l == 1) {
            gridbar();   // xbuf1 complete
            #pragma unroll 1
            for (int tt = 0; tt < 4; tt++) {
                int tile = bid*4 + tt;
                int d2 = tile >> 8, j = tile & 255;
                gemm512(g_xbuf1, 1024, enc_Wih + (size_t)(2 + d2)*2048*1024, 1024,
                        enc_b + (2 + d2)*2048, g_gatesin + (size_t)d2*2048*2048, 2048, 1024,
                        j >> 4, j & 15);
            }
            gridbar();
        }
        const float* WhhT = g_WhhEncT + (size_t)(l*2 + d)*512*2048;
        const float* gin  = g_gatesin + (size_t)d*2048*2048;
        float* xout = l ? g_xbuf0 : g_xbuf1;
        float creg[2] = {0.f, 0.f};

        for (int s = 0; s <= 128; s++) {
            #pragma unroll
            for (int j = 0; j < 2; j++) {
                int i2 = tid + 512*j;
                int b = i2 >> 6, k = i2 & 63;
                int hh = kc*64 + k;
                float v;
                if (s == 0) { v = 0.f; creg[j] = 0.f; }
                else {
                    int sp = s - 1;
                    int sdir = d ? (127 - sp) : sp;
                    const float* gr = gin + ((size_t)b*128 + sdir)*2048;
                    const float* ep = g_epart + (size_t)(sp & 1)*524288 + (size_t)(d*8)*16*2048;
                    float g4[4];
                    #pragma unroll
                    for (int q = 0; q < 4; q++) {
                        int col = q*512 + hh;
                        float x = gr[col];
                        #pragma unroll
                        for (int p = 0; p < 8; p++) x += ep[(size_t)(p*16 + b)*2048 + col];
                        g4[q] = x;
                    }
                    v = lstm_h(g4, creg[j]);
                    if (nc == 0) {
                        xout[((size_t)b*128 + sdir)*1024 + d*512 + hh] = v;
                        if (s == 128) {
                            g_hdec[l*16384 + b*1024 + d*512 + hh] = v;
                            g_cdec[l*16384 + b*1024 + d*512 + hh] = creg[j];
                        }
                    }
                }
                if (s < 128) sb[k*18 + b] = v;
            }
            if (s == 128) break;
            __syncthreads();
            gemv4x2<64>(WhhT + (size_t)(kc*64)*2048 + n4, 2048, sb, bp,
                        g_epart + (size_t)(s & 1)*524288 + (size_t)((d*8 + kc)*16 + 2*bp)*2048 + n4,
                        2048);
            gridbar();
        }
    }
    gridbar();   // xbuf0 (enc output) complete
    gemm512(g_xbuf0, 1024, g_lininT, 1024, g_zero, g_encW, 1024, 1024, bid >> 3, bid & 7);
}

// ---------------- persistent decoder: 128 x 512, 5 phases/step ----------------
__global__ void __launch_bounds__(512, 1) k_dec_persist(const float* __restrict__ bias1) {
    __shared__ float sb[4608];
    int tid = threadIdx.x, bid = blockIdx.x;
    int kcA = bid & 7, ncA = bid >> 3;
    int kcG = bid & 15, ncG = bid >> 4;
    int bF = bid >> 3, sg = bid & 7;
    int bp = tid & 7, ng = tid >> 3;
    int n4 = ncA*256 + ng*4;
    int n2 = ncG*128 + ng*2;

    float cd0[8];
    if (kcA < 4) {
        #pragma unroll
        for (int j = 0; j < 8; j++) {
            int i2 = tid + 512*j;
            int b = i2 >> 8, k = i2 & 255;
            cd0[j] = g_cdec[b*1024 + kcA*256 + k];
        }
    }
    float cd1f[2];
    cd1f[0] = g_cdec[16384 + bF*1024 + tid];
    cd1f[1] = g_cdec[16384 + bF*1024 + tid + 512];

    for (int t = 0; t < 128; t++) {
        // ---- Phase A: stage [op(t-1) ; hd0(t-1)] -> part0 ----
        #pragma unroll
        for (int j = 0; j < 8; j++) {
            int i2 = tid + 512*j;
            int b = i2 >> 8, k = i2 & 255;
            int kg = kcA*256 + k;
            float v;
            if (kcA < 4) v = t ? g_op[b*1024 + kg] : 0.f;
            else {
                int hh = kg - 1024;
                v = t ? g_hd0[b*1024 + hh] : g_hdec[b*1024 + hh];
            }
            sb[k*18 + b] = v;
        }
        __syncthreads();
        gemv4x2<256>(g_WdecT0 + (size_t)(kcA*256)*4096 + n4, 4096, sb, bp,
                     g_part0 + (size_t)(kcA*16 + 2*bp)*4096 + n4, 4096);
        gridbar();
        // ---- Phase C: stage [cell0(t) ; hd1(t-1)] -> part1 ----
        #pragma unroll
        for (int j = 0; j < 8; j++) {
            int i2 = tid + 512*j;
            int b = i2 >> 8, k = i2 & 255;
            int kg = kcA*256 + k;
            float v;
            if (kcA < 4) {
                const float* pl = g_preL0 + ((size_t)b*128 + t)*4096;
                float g4[4];
                #pragma unroll
                for (int q = 0; q < 4; q++) {
                    int col = q*1024 + kg;
                    float x = pl[col];
                    #pragma unroll
                    for (int p = 0; p < 8; p++) x += g_part0[(size_t)(p*16 + b)*4096 + col];
                    g4[q] = x;
                }
                v = lstm_h(g4, cd0[j]);
                if (ncA == 0) g_hd0[b*1024 + kg] = v;
            } else {
                int hh = kg - 1024;
                v = t ? g_hd1[b*1024 + hh] : g_hdec[16384 + b*1024 + hh];
            }
            sb[k*18 + b] = v;
        }
        __syncthreads();
        gemv4x2<256>(g_WdecT1 + (size_t)(kcA*256)*4096 + n4, 4096, sb, bp,
                     g_part1 + (size_t)(kcA*16 + 2*bp)*4096 + n4, 4096);
        gridbar();
        // ---- Phase F: cell1(t) -> hd1, scores, softmax, context ----
        #pragma unroll
        for (int j = 0; j < 2; j++) {
            int hh = tid + 512*j;
            float g4[4];
            #pragma unroll
            for (int q = 0; q < 4; q++) {
                int col = q*1024 + hh;
                float x = bias1[col];
                #pragma unroll
                for (int p = 0; p < 8; p++) x += g_part1[(size_t)(p*16 + bF)*4096 + col];
                g4[q] = x;
            }
            float v = lstm_h(g4, cd1f[j]);
            sb[hh] = v;
            if (sg == 0) g_hd1[bF*1024 + hh] = v;
        }
        __syncthreads();
        {
            int w = tid >> 5, lane = tid & 31;
            float* sc = sb + 1024;
            #pragma unroll 1
            for (int j2 = 0; j2 < 8; j2++) {
                int s = w*8 + j2;
                const float* er = g_encW + ((size_t)bF*128 + s)*1024;
                float a = 0.f;
                #pragma unroll 8
                for (int k = lane; k < 1024; k += 32) a += er[k] * sb[k];
                #pragma unroll
                for (int o = 16; o; o >>= 1) a += __shfl_xor_sync(0xffffffffu, a, o);
                if (!lane) sc[s] = a;
            }
        }
        __syncthreads();
        if (tid < 32) {
            float* sc = sb + 1024;
            float m = -1e30f;
            #pragma unroll
            for (int s = tid; s < 128; s += 32) m = fmaxf(m, sc[s]);
            #pragma unroll
            for (int o = 16; o; o >>= 1) m = fmaxf(m, __shfl_xor_sync(0xffffffffu, m, o));
            float sum = 0.f;
            #pragma unroll
            for (int s = tid; s < 128; s += 32) { float e2 = expf(sc[s]-m); sc[s] = e2; sum += e2; }
            #pragma unroll
            for (int o = 16; o; o >>= 1) sum += __shfl_xor_sync(0xffffffffu, sum, o);
            float inv = 1.f / sum;
            #pragma unroll
            for (int s = tid; s < 128; s += 32) sc[s] *= inv;
        }
        __syncthreads();
        {
            const float* sc = sb + 1024;
            float* pc = sb + 1152;
            int hoff = tid & 127, squad = tid >> 7;
            int h = sg*128 + hoff;
            const float* e = g_xbuf0 + ((size_t)bF*128 + squad*32)*1024 + h;
            float a = 0.f;
            #pragma unroll 8
            for (int s = 0; s < 32; s++) a += sc[squad*32 + s] * e[(size_t)s*1024];
            pc[tid] = a;
            __syncthreads();
            if (tid < 128)
                g_cc[bF*1024 + sg*128 + tid] = pc[tid] + pc[tid+128] + pc[tid+256] + pc[tid+384];
        }
        gridbar();
        // ---- Phase G: linout partials from [cc ; hd1] ----
        #pragma unroll
        for (int j = 0; j < 4; j++) {
            int i2 = tid + 512*j;
            int b = i2 >> 7, k = i2 & 127;
            int kg = kcG*128 + k;
            sb[k*18 + b] = (kg < 1024) ? g_cc[b*1024 + kg] : g_hd1[b*1024 + kg - 1024];
        }
        __syncthreads();
        {
            float2 a0 = make_float2(0.f,0.f), a1 = a0;
            const float* wp = g_linoutT + (size_t)(kcG*128)*1024 + n2;
            #pragma unroll 8
            for (int k = 0; k < 128; k++) {
                float2 w2 = *(const float2*)(wp + (size_t)k*1024);
                float2 bv = *(const float2*)&sb[k*18 + 2*bp];
                a0 = ffma2(make_float2(w2.x, w2.x), bv, a0);
                a1 = ffma2(make_float2(w2.y, w2.y), bv, a1);
            }
            float* pp = g_lopart + (size_t)(kcG*16 + 2*bp)*1024 + n2;
            pp[0] = a0.x; pp[1] = a1.x;
            pp[1024] = a0.y; pp[1025] = a1.y;
        }
        gridbar();
        // ---- Phase H: opn = tanh(sum), op ----
        if (tid < 128) {
            int gi2 = bid*128 + tid;
            int b = gi2 >> 10, hh = gi2 & 1023;
            float v = 0.f;
            #pragma unroll
            for (int p = 0; p < 16; p++) v += g_lopart[(size_t)(p*16 + b)*1024 + hh];
            float o = tanhf(v);
            g_op[b*1024 + hh] = o;
            g_opn[((size_t)b*128 + t)*1024 + hh] = o;
        }
        gridbar();
    }
}

// ---------------- host ----------------
extern "C" void kernel_launch(void* const* d_in, const int* in_sizes, int n_in,
                              void* d_out, int out_size) {
    const float* enc_emb      = (const float*)d_in[0];
    const float* dec_emb      = (const float*)d_in[1];
    const float* enc_Wih      = (const float*)d_in[2];
    const float* enc_Whh      = (const float*)d_in[3];
    const float* enc_b        = (const float*)d_in[4];
    const float* dec_Wih0     = (const float*)d_in[5];
    const float* dec_Wih_rest = (const float*)d_in[6];
    const float* dec_Whh      = (const float*)d_in[7];
    const float* dec_b        = (const float*)d_in[8];
    const float* linin_W      = (const float*)d_in[9];
    const float* linout_W     = (const float*)d_in[10];
    const float* gen_W        = (const float*)d_in[11];
    const float* gen_b        = (const float*)d_in[12];
    const int*   inp          = (const int*)d_in[13];
    const int*   outtok       = (const int*)d_in[14];
    float* logits = (float*)d_out;

    // 0: prep
    k_prep<<<39936, 256>>>(enc_emb, dec_emb, enc_Whh, dec_Wih0, dec_Wih_rest,
                           dec_Whh, linin_W, linout_W, inp, outtok);
    // 1: enc layer-0 gates (fp32) + preL0 (tf32)
    k_gemmA<<<1024, 512>>>(enc_Wih, enc_b, dec_Wih0, dec_b);
    // 2: encoder (both layers + L1 gates + encW)
    k_encAll<<<128, 512>>>(enc_Wih, enc_b);
    // 3: decoder (profiled index)
    k_dec_persist<<<128, 512>>>(dec_b + 4096);
    // 4: generator (tf32 tensor cores)
    k_gemmGen<<<dim3(250, 16), 512>>>(gen_W, gen_b, logits);
}